// round 10
// baseline (speedup 1.0000x reference)
#include <cuda_runtime.h>
#include <cuda_bf16.h>
#include <math.h>
#include <stdint.h>

// Problem constants
#define BB 2048
#define KK 64
#define DIN 768
#define CF 64
#define MROWS (BB*KK)
#define SHARPNESS 1048576.0f
#define NCH 12            // K chunks of 64
#define CAND_TH 0.03f     // approx-score gap threshold for refinement

// ---------------- scratch ----------------
__device__ float g_xfeat[BB*CF];
__device__ float g_scores[MROWS];        // approx scores (1-term bf16)
__device__ float g_exact[MROWS];         // exact scores for candidates, -1e30 else
__device__ int   g_list[MROWS];          // candidate list (b*64+k)
__device__ int   g_count;
__device__ float g_WphiT[DIN*CF];        // Wphi transposed [k][f], fp32
// Fragment-ordered bf16 HI images of Wphi: [c][ks][nt][lane] uint2 {h01,h23}
__device__ __align__(16) uint2 g_Bfrag[NCH*4*8*32];   // 98KB, L2-resident

// ---------------- helpers ----------------
__device__ __forceinline__ void cpa16(void* smem, const void* g) {
    unsigned s = (unsigned)__cvta_generic_to_shared(smem);
    asm volatile("cp.async.cg.shared.global [%0], [%1], 16;" :: "r"(s), "l"(g));
}
#define CP_COMMIT() asm volatile("cp.async.commit_group;")
#define CP_WAIT1()  asm volatile("cp.async.wait_group 1;" ::: "memory")

__device__ __forceinline__ uint32_t cvt_hi(float a0, float a1) {
    uint32_t hp;
    asm("cvt.rn.satfinite.bf16x2.f32 %0, %1, %2;" : "=r"(hp) : "f"(a1), "f"(a0));
    return hp;
}

__device__ __forceinline__ void mma_bf16(float* d, const uint32_t* a, uint32_t b0, uint32_t b1) {
    asm volatile("mma.sync.aligned.m16n8k16.row.col.f32.bf16.bf16.f32 "
        "{%0,%1,%2,%3}, {%4,%5,%6,%7}, {%8,%9}, {%0,%1,%2,%3};"
        : "+f"(d[0]), "+f"(d[1]), "+f"(d[2]), "+f"(d[3])
        : "r"(a[0]), "r"(a[1]), "r"(a[2]), "r"(a[3]), "r"(b0), "r"(b1));
}

// ---------------- kernel E: Wphi -> fragment-ordered bf16 hi ----------------
__global__ void kernE(const float* __restrict__ Wphi) {
    int idx = blockIdx.x * 256 + threadIdx.x;    // < 12288
    int lane = idx & 31;
    int t = idx >> 5;                            // c*32 + ks*8 + nt
    int nt = t & 7, ks = (t >> 3) & 3, c = t >> 5;
    int g = lane >> 2, tig = lane & 3;
    int n = nt * 8 + g;
    int k0 = c * 64 + ks * 16 + 2 * tig;
    const float* wr = Wphi + n * DIN + k0;
    uint32_t h01 = cvt_hi(wr[0], wr[1]);
    uint32_t h23 = cvt_hi(wr[8], wr[9]);
    g_Bfrag[((c * 4 + ks) * 8 + nt) * 32 + lane] = make_uint2(h01, h23);
}

// ---------------- kernel E2: WphiT fp32 + zero candidate count ----------------
__global__ void kernE2(const float* __restrict__ Wphi) {
    int o = blockIdx.x * 256 + threadIdx.x;      // o = k*64+f, < 49152
    if (o == 0) g_count = 0;
    int k = o >> 6, f = o & 63;
    g_WphiT[o] = Wphi[f * DIN + k];
}

// ---------------- kernel A: x_feat = l2norm(x_im @ Wtheta^T + btheta) ----------------
__global__ void __launch_bounds__(256) kernA(const float* __restrict__ xim,
                                             const float* __restrict__ Wtheta,
                                             const float* __restrict__ btheta) {
    __shared__ __align__(16) float xs[8 * DIN];
    __shared__ float wred[8][2];
    int tid = threadIdx.x;
    int b0 = blockIdx.x * 8;
    const float4* src = (const float4*)(xim + (size_t)b0 * DIN);
    float4* d4 = (float4*)xs;
#pragma unroll
    for (int j = 0; j < 6; j++) d4[tid + 256 * j] = src[tid + 256 * j];
    __syncthreads();
    int f = tid & 63, g = tid >> 6;
    const float* wr = Wtheta + (size_t)f * DIN;
    const float* xa = xs + (2 * g) * DIN;
    const float* xb = xs + (2 * g + 1) * DIN;
    float a0 = 0.f, a1 = 0.f;
    for (int i = 0; i < DIN; i += 4) {
        float4 w4 = *(const float4*)(wr + i);
        float4 va = *(const float4*)(xa + i);
        float4 vb = *(const float4*)(xb + i);
        a0 += w4.x * va.x + w4.y * va.y + w4.z * va.z + w4.w * va.w;
        a1 += w4.x * vb.x + w4.y * vb.y + w4.z * vb.z + w4.w * vb.w;
    }
    a0 += btheta[f]; a1 += btheta[f];
    float s0 = a0 * a0, s1 = a1 * a1;
#pragma unroll
    for (int o = 1; o < 32; o <<= 1) {
        s0 += __shfl_xor_sync(0xffffffffu, s0, o);
        s1 += __shfl_xor_sync(0xffffffffu, s1, o);
    }
    int w = tid >> 5;
    if ((tid & 31) == 0) { wred[w][0] = s0; wred[w][1] = s1; }
    __syncthreads();
    int wb = g << 1;
    float n0 = wred[wb][0] + wred[wb + 1][0];
    float n1 = wred[wb][1] + wred[wb + 1][1];
    g_xfeat[(b0 + 2 * g) * CF + f]     = a0 / fmaxf(sqrtf(n0), 1e-12f);
    g_xfeat[(b0 + 2 * g + 1) * CF + f] = a1 / fmaxf(sqrtf(n1), 1e-12f);
}

// ---------------- kernel B: 1-term bf16 HMMA approx GEMM + score epilogue ----------------
#define ASTR 68                 // fp32 row stride in smem (272B = 17x16B)
#define S_A  0                  // 2 stages x 128*68*4 = 69632
#define S_B  69632              // 2 stages x 8KB = 16384
#define S_XF 86016              // 512
#define S_BP 86528              // 256
#define SMEMB_TOTAL 86784

__global__ void __launch_bounds__(256, 2) kernB(const float* __restrict__ pim,
                                                const float* __restrict__ bphi) {
    extern __shared__ __align__(16) char smem[];
    float* Asm = (float*)(smem + S_A);               // [2][128*ASTR]
    uint2* Bsm = (uint2*)(smem + S_B);               // [2][1024]
    float* xfsm = (float*)(smem + S_XF);
    float* bpsm = (float*)(smem + S_BP);

    int tid = threadIdx.x, w = tid >> 5, lane = tid & 31;
    int g = lane >> 2, tig = lane & 3;
    int m0 = blockIdx.x * 128;
    if (tid < 128) xfsm[tid] = g_xfeat[m0 + tid];
    else if (tid < 192) bpsm[tid - 128] = bphi[tid - 128];

    float acc[8][4];
#pragma unroll
    for (int nt = 0; nt < 8; nt++)
#pragma unroll
        for (int i = 0; i < 4; i++) acc[nt][i] = 0.f;

    const int arow = (tid >> 4);
    const int acol = 4 * (tid & 15);
    const float* asrc = pim + (size_t)(m0 + arow) * DIN + acol;

    auto issue = [&](int c, int s) {
        float* Ad = Asm + s * (128 * ASTR);
#pragma unroll
        for (int i = 0; i < 8; i++)
            cpa16(Ad + (arow + 16 * i) * ASTR + acol, asrc + (size_t)16 * i * DIN + c * 64);
        const char* bs = (const char*)(g_Bfrag + (size_t)c * 1024) + tid * 32;
        char* bd = (char*)(Bsm + s * 1024) + tid * 32;
        cpa16(bd, bs); cpa16(bd + 16, bs + 16);
        CP_COMMIT();
    };

    issue(0, 0); issue(1, 1);

    for (int c = 0; c < NCH; c++) {
        const int s = c & 1;
        CP_WAIT1();
        __syncthreads();
        const float* As = Asm + s * (128 * ASTR);
        const uint2* Bs = Bsm + s * 1024;
        const int r0 = 16 * w + g;
#pragma unroll
        for (int ks = 0; ks < 4; ks++) {
            const int kb = 16 * ks + 2 * tig;
            float2 f0 = *(const float2*)(As + r0 * ASTR + kb);
            float2 f1 = *(const float2*)(As + (r0 + 8) * ASTR + kb);
            float2 f2 = *(const float2*)(As + r0 * ASTR + kb + 8);
            float2 f3 = *(const float2*)(As + (r0 + 8) * ASTR + kb + 8);
            uint32_t Ah[4];
            Ah[0] = cvt_hi(f0.x, f0.y);
            Ah[1] = cvt_hi(f1.x, f1.y);
            Ah[2] = cvt_hi(f2.x, f2.y);
            Ah[3] = cvt_hi(f3.x, f3.y);
#pragma unroll
            for (int nt = 0; nt < 8; nt++) {
                uint2 b = Bs[(ks * 8 + nt) * 32 + lane];
                mma_bf16(acc[nt], Ah, b.x, b.y);
            }
        }
        __syncthreads();
        if (c + 2 < NCH) issue(c + 2, s);
        else CP_COMMIT();
    }

    // Epilogue: u = D + bphi; approx score = dot(xf,u)/max(||u||,1e-12)
    int bi = w >> 2;
    float ps0 = 0.f, pd0 = 0.f, ps1 = 0.f, pd1 = 0.f;
#pragma unroll
    for (int nt = 0; nt < 8; nt++) {
        int col = nt * 8 + 2 * tig;
        float b0 = bpsm[col], b1 = bpsm[col + 1];
        float x0 = xfsm[bi * 64 + col], x1 = xfsm[bi * 64 + col + 1];
        float u;
        u = acc[nt][0] + b0; ps0 += u * u; pd0 += u * x0;
        u = acc[nt][1] + b1; ps0 += u * u; pd0 += u * x1;
        u = acc[nt][2] + b0; ps1 += u * u; pd1 += u * x0;
        u = acc[nt][3] + b1; ps1 += u * u; pd1 += u * x1;
    }
#pragma unroll
    for (int o = 1; o < 4; o <<= 1) {
        ps0 += __shfl_xor_sync(0xffffffffu, ps0, o);
        pd0 += __shfl_xor_sync(0xffffffffu, pd0, o);
        ps1 += __shfl_xor_sync(0xffffffffu, ps1, o);
        pd1 += __shfl_xor_sync(0xffffffffu, pd1, o);
    }
    if (tig == 0) {
        int r = m0 + 16 * w + g;
        g_scores[r]     = pd0 / fmaxf(sqrtf(ps0), 1e-12f);
        g_scores[r + 8] = pd1 / fmaxf(sqrtf(ps1), 1e-12f);
    }
}

// ---------------- kernel C1: candidate selection ----------------
__global__ void __launch_bounds__(256) kernC1() {
    int warp = threadIdx.x >> 5, lane = threadIdx.x & 31;
    int b = blockIdx.x * 8 + warp;
    float s0 = g_scores[b * 64 + lane];
    float s1 = g_scores[b * 64 + 32 + lane];
    float m = fmaxf(s0, s1);
#pragma unroll
    for (int o = 16; o >= 1; o >>= 1) m = fmaxf(m, __shfl_xor_sync(0xffffffffu, m, o));
    float th = m - CAND_TH;
    g_exact[b * 64 + lane]      = -1e30f;
    g_exact[b * 64 + 32 + lane] = -1e30f;
    if (s0 >= th) { int pos = atomicAdd(&g_count, 1); g_list[pos] = b * 64 + lane; }
    if (s1 >= th) { int pos = atomicAdd(&g_count, 1); g_list[pos] = b * 64 + 32 + lane; }
}

// ---------------- kernel R: exact fp32 refinement of candidates ----------------
// 8 candidates per block iteration; 256 threads: group g=tid/64 handles cands g and g+4,
// feature f = tid%64.
__global__ void __launch_bounds__(256) kernR(const float* __restrict__ pim,
                                             const float* __restrict__ bphi) {
    __shared__ __align__(16) float psm[8][DIN];   // 24KB
    __shared__ float redp[8][2], redd[8][2];
    __shared__ int lsm[8];
    int tid = threadIdx.x;
    int cnt = g_count;

    for (int base = blockIdx.x * 8; base < cnt; base += gridDim.x * 8) {
        int nc = min(8, cnt - base);
        __syncthreads();          // protect smem reuse from previous iteration
        if (tid < 8) lsm[tid] = (tid < nc) ? g_list[base + tid] : -1;
        __syncthreads();
        // stage p rows (coalesced): 32 threads per row
        int row = tid >> 5, lj = tid & 31;
        if (row < nc) {
            const float4* src = (const float4*)(pim + (size_t)lsm[row] * DIN);
            float4* dst = (float4*)&psm[row][0];
#pragma unroll
            for (int jj = 0; jj < 6; jj++) dst[lj + 32 * jj] = src[lj + 32 * jj];
        }
        __syncthreads();

        int f = tid & 63, g = tid >> 6;
        float u0 = 0.f, u1 = 0.f;
#pragma unroll 4
        for (int k = 0; k < DIN; k++) {
            float wv = g_WphiT[k * 64 + f];
            u0 += wv * psm[g][k];
            u1 += wv * psm[g + 4][k];
        }
        float bp = bphi[f];
        u0 += bp; u1 += bp;

        int bk0 = lsm[g], bk1 = lsm[g + 4];
        float xf0 = (bk0 >= 0) ? g_xfeat[(bk0 >> 6) * 64 + f] : 0.f;
        float xf1 = (bk1 >= 0) ? g_xfeat[(bk1 >> 6) * 64 + f] : 0.f;
        float ps0 = u0 * u0, pd0 = u0 * xf0;
        float ps1 = u1 * u1, pd1 = u1 * xf1;
#pragma unroll
        for (int o = 16; o >= 1; o >>= 1) {
            ps0 += __shfl_xor_sync(0xffffffffu, ps0, o);
            pd0 += __shfl_xor_sync(0xffffffffu, pd0, o);
            ps1 += __shfl_xor_sync(0xffffffffu, ps1, o);
            pd1 += __shfl_xor_sync(0xffffffffu, pd1, o);
        }
        if ((tid & 31) == 0) {
            int h = (tid >> 5) & 1;
            redp[g][h] = ps0;     redd[g][h] = pd0;
            redp[g + 4][h] = ps1; redd[g + 4][h] = pd1;
        }
        __syncthreads();
        if (tid < 8 && lsm[tid] >= 0) {
            float ps = redp[tid][0] + redp[tid][1];
            float pd = redd[tid][0] + redd[tid][1];
            g_exact[lsm[tid]] = pd / fmaxf(sqrtf(ps), 1e-12f);
        }
    }
}

// ---------------- kernel D: fused softmax (exact scores) + weighted sum + mix + blend ----------------
__global__ void __launch_bounds__(192) kernD(const float* __restrict__ x,
                                             const float* __restrict__ p,
                                             const float* __restrict__ Wg,
                                             const float* __restrict__ bgv,
                                             const float* __restrict__ Wo,
                                             const float* __restrict__ bov,
                                             const float* __restrict__ sig_scale,
                                             const float* __restrict__ sig_shift,
                                             float* __restrict__ out) {
    __shared__ __align__(16) float buf[DIN];
    __shared__ __align__(16) float wsm[64];
    __shared__ float swsm;
    int tid = threadIdx.x;
    int b = blockIdx.x;

    if (tid < 32) {
        int lane = tid;
        float s0 = g_exact[b * 64 + lane];
        float s1 = g_exact[b * 64 + 32 + lane];
        float t0 = s0 * SHARPNESS, t1 = s1 * SHARPNESS;
        float mraw = fmaxf(s0, s1), mt = fmaxf(t0, t1);
#pragma unroll
        for (int o = 16; o >= 1; o >>= 1) {
            mraw = fmaxf(mraw, __shfl_xor_sync(0xffffffffu, mraw, o));
            mt   = fmaxf(mt,   __shfl_xor_sync(0xffffffffu, mt, o));
        }
        float e0 = expf(t0 - mt), e1 = expf(t1 - mt);
        float sum = e0 + e1;
#pragma unroll
        for (int o = 16; o >= 1; o >>= 1) sum += __shfl_xor_sync(0xffffffffu, sum, o);
        float inv = 1.f / sum;
        wsm[lane]      = e0 * inv;
        wsm[lane + 32] = e1 * inv;
        if (lane == 0) {
            float z = mraw * sig_scale[0] + sig_shift[0];
            swsm = 1.f / (1.f + expf(-z));
        }
    }
    __syncthreads();

    float4 acc = make_float4(0.f, 0.f, 0.f, 0.f);
    const float4* pb = (const float4*)(p + (size_t)b * KK * DIN);
    for (int k = 0; k < 64; k++) {
        float w = wsm[k];
        if (w > 1e-10f) {
            float4 v = pb[k * 192 + tid];
            acc.x += w * v.x; acc.y += w * v.y; acc.z += w * v.z; acc.w += w * v.w;
        }
    }
    ((float4*)buf)[tid] = acc;
    __syncthreads();

    int o = tid / 64;
    int hw = (tid % 64) * 4;
    float gg0 = Wg[o * 3 + 0], gg1 = Wg[o * 3 + 1], gg2 = Wg[o * 3 + 2];
    float bgc = bgv[o];
    float t[4];
#pragma unroll
    for (int j = 0; j < 4; j++)
        t[j] = gg0 * buf[hw + j] + gg1 * buf[256 + hw + j] + gg2 * buf[512 + hw + j] + bgc;
    __syncthreads();
#pragma unroll
    for (int j = 0; j < 4; j++) buf[o * 256 + hw + j] = t[j];
    __syncthreads();

    float oo0 = Wo[o * 3 + 0], oo1 = Wo[o * 3 + 1], oo2 = Wo[o * 3 + 2];
    float boc = bov[o];
    float sw = swsm;
    float4 xv = ((const float4*)(x + (size_t)b * DIN))[tid];
    float pa0 = oo0 * buf[hw + 0] + oo1 * buf[256 + hw + 0] + oo2 * buf[512 + hw + 0] + boc;
    float pa1 = oo0 * buf[hw + 1] + oo1 * buf[256 + hw + 1] + oo2 * buf[512 + hw + 1] + boc;
    float pa2 = oo0 * buf[hw + 2] + oo1 * buf[256 + hw + 2] + oo2 * buf[512 + hw + 2] + boc;
    float pa3 = oo0 * buf[hw + 3] + oo1 * buf[256 + hw + 3] + oo2 * buf[512 + hw + 3] + boc;
    float4 ov;
    ov.x = xv.x * (1.f - sw) + pa0 * sw;
    ov.y = xv.y * (1.f - sw) + pa1 * sw;
    ov.z = xv.z * (1.f - sw) + pa2 * sw;
    ov.w = xv.w * (1.f - sw) + pa3 * sw;
    ((float4*)(out + (size_t)b * DIN))[tid] = ov;
}

// ---------------- launch ----------------
extern "C" void kernel_launch(void* const* d_in, const int* in_sizes, int n_in,
                              void* d_out, int out_size) {
    const float* x         = (const float*)d_in[0];
    const float* p         = (const float*)d_in[1];
    const float* x_im      = (const float*)d_in[2];
    const float* p_im      = (const float*)d_in[3];
    const float* Wtheta    = (const float*)d_in[4];
    const float* btheta    = (const float*)d_in[5];
    const float* Wphi      = (const float*)d_in[6];
    const float* bphi      = (const float*)d_in[7];
    const float* Wg        = (const float*)d_in[8];
    const float* bg        = (const float*)d_in[9];
    const float* Wo        = (const float*)d_in[10];
    const float* bo        = (const float*)d_in[11];
    const float* sig_scale = (const float*)d_in[12];
    const float* sig_shift = (const float*)d_in[13];
    float* out = (float*)d_out;

    cudaFuncSetAttribute(kernB, cudaFuncAttributeMaxDynamicSharedMemorySize, SMEMB_TOTAL);

    kernE<<<48, 256>>>(Wphi);
    kernE2<<<192, 256>>>(Wphi);
    kernA<<<BB / 8, 256>>>(x_im, Wtheta, btheta);
    kernB<<<MROWS / 128, 256, SMEMB_TOTAL>>>(p_im, bphi);
    kernC1<<<BB / 8, 256>>>();
    kernR<<<512, 256>>>(p_im, bphi);
    kernD<<<BB, 192>>>(x, p, Wg, bg, Wo, bo, sig_scale, sig_shift, out);
}

// round 12
// speedup vs baseline: 1.2517x; 1.2517x over previous
#include <cuda_runtime.h>
#include <cuda_bf16.h>
#include <math.h>
#include <stdint.h>

// Problem constants
#define BB 2048
#define KK 64
#define DIN 768
#define CF 64
#define MROWS (BB*KK)
#define SHARPNESS 1048576.0f
#define NCH 12            // K chunks of 64
#define CAND_TH 0.03f     // approx-score gap threshold for refinement

// ---------------- scratch ----------------
__device__ float g_xfeat[BB*CF];
__device__ float g_scores[MROWS];        // approx scores (1-term bf16)
__device__ float g_exact[MROWS];         // exact scores for candidates, -1e30 else
__device__ int   g_list[MROWS];          // candidate list (b*64+k)
__device__ int   g_count;
__device__ float g_WphiT[DIN*CF];        // Wphi transposed [k][f], fp32
// Fragment-ordered bf16 HI images of Wphi: [c][ks][nt][lane] uint2 {h01,h23}
__device__ __align__(16) uint2 g_Bfrag[NCH*4*8*32];   // 98KB, L2-resident

// ---------------- helpers ----------------
__device__ __forceinline__ void cpa16(void* smem, const void* g) {
    unsigned s = (unsigned)__cvta_generic_to_shared(smem);
    asm volatile("cp.async.cg.shared.global [%0], [%1], 16;" :: "r"(s), "l"(g));
}
#define CP_COMMIT() asm volatile("cp.async.commit_group;")
#define CP_WAIT1()  asm volatile("cp.async.wait_group 1;" ::: "memory")

__device__ __forceinline__ uint32_t cvt_hi(float a0, float a1) {
    uint32_t hp;
    asm("cvt.rn.satfinite.bf16x2.f32 %0, %1, %2;" : "=r"(hp) : "f"(a1), "f"(a0));
    return hp;
}

__device__ __forceinline__ void mma_bf16(float* d, const uint32_t* a, uint32_t b0, uint32_t b1) {
    asm volatile("mma.sync.aligned.m16n8k16.row.col.f32.bf16.bf16.f32 "
        "{%0,%1,%2,%3}, {%4,%5,%6,%7}, {%8,%9}, {%0,%1,%2,%3};"
        : "+f"(d[0]), "+f"(d[1]), "+f"(d[2]), "+f"(d[3])
        : "r"(a[0]), "r"(a[1]), "r"(a[2]), "r"(a[3]), "r"(b0), "r"(b1));
}

// ---------------- kernel E: Wphi -> fragment-ordered bf16 hi ----------------
__global__ void kernE(const float* __restrict__ Wphi) {
    int idx = blockIdx.x * 256 + threadIdx.x;    // < 12288
    int lane = idx & 31;
    int t = idx >> 5;                            // c*32 + ks*8 + nt
    int nt = t & 7, ks = (t >> 3) & 3, c = t >> 5;
    int g = lane >> 2, tig = lane & 3;
    int n = nt * 8 + g;
    int k0 = c * 64 + ks * 16 + 2 * tig;
    const float* wr = Wphi + n * DIN + k0;
    uint32_t h01 = cvt_hi(wr[0], wr[1]);
    uint32_t h23 = cvt_hi(wr[8], wr[9]);
    g_Bfrag[((c * 4 + ks) * 8 + nt) * 32 + lane] = make_uint2(h01, h23);
}

// ---------------- kernel E2: WphiT fp32 + zero candidate count ----------------
__global__ void kernE2(const float* __restrict__ Wphi) {
    int o = blockIdx.x * 256 + threadIdx.x;      // o = k*64+f, < 49152
    if (o == 0) g_count = 0;
    int k = o >> 6, f = o & 63;
    g_WphiT[o] = Wphi[f * DIN + k];
}

// ---------------- kernel A: x_feat = l2norm(x_im @ Wtheta^T + btheta) ----------------
__global__ void __launch_bounds__(256) kernA(const float* __restrict__ xim,
                                             const float* __restrict__ Wtheta,
                                             const float* __restrict__ btheta) {
    __shared__ __align__(16) float xs[8 * DIN];
    __shared__ float wred[8][2];
    int tid = threadIdx.x;
    int b0 = blockIdx.x * 8;
    const float4* src = (const float4*)(xim + (size_t)b0 * DIN);
    float4* d4 = (float4*)xs;
#pragma unroll
    for (int j = 0; j < 6; j++) d4[tid + 256 * j] = src[tid + 256 * j];
    __syncthreads();
    int f = tid & 63, g = tid >> 6;
    const float* wr = Wtheta + (size_t)f * DIN;
    const float* xa = xs + (2 * g) * DIN;
    const float* xb = xs + (2 * g + 1) * DIN;
    float a0 = 0.f, a1 = 0.f;
    for (int i = 0; i < DIN; i += 4) {
        float4 w4 = *(const float4*)(wr + i);
        float4 va = *(const float4*)(xa + i);
        float4 vb = *(const float4*)(xb + i);
        a0 += w4.x * va.x + w4.y * va.y + w4.z * va.z + w4.w * va.w;
        a1 += w4.x * vb.x + w4.y * vb.y + w4.z * vb.z + w4.w * vb.w;
    }
    a0 += btheta[f]; a1 += btheta[f];
    float s0 = a0 * a0, s1 = a1 * a1;
#pragma unroll
    for (int o = 1; o < 32; o <<= 1) {
        s0 += __shfl_xor_sync(0xffffffffu, s0, o);
        s1 += __shfl_xor_sync(0xffffffffu, s1, o);
    }
    int w = tid >> 5;
    if ((tid & 31) == 0) { wred[w][0] = s0; wred[w][1] = s1; }
    __syncthreads();
    int wb = g << 1;
    float n0 = wred[wb][0] + wred[wb + 1][0];
    float n1 = wred[wb][1] + wred[wb + 1][1];
    g_xfeat[(b0 + 2 * g) * CF + f]     = a0 / fmaxf(sqrtf(n0), 1e-12f);
    g_xfeat[(b0 + 2 * g + 1) * CF + f] = a1 / fmaxf(sqrtf(n1), 1e-12f);
}

// ---------------- kernel B: 1-term bf16 HMMA approx GEMM + score epilogue ----------------
#define ASTR 68                 // fp32 row stride in smem (272B = 17x16B)
#define S_A  0                  // 2 stages x 128*68*4 = 69632
#define S_B  69632              // 2 stages x 8KB = 16384
#define S_XF 86016              // 512
#define S_BP 86528              // 256
#define SMEMB_TOTAL 86784

__global__ void __launch_bounds__(256, 2) kernB(const float* __restrict__ pim,
                                                const float* __restrict__ bphi) {
    extern __shared__ __align__(16) char smem[];
    float* Asm = (float*)(smem + S_A);               // [2][128*ASTR]
    uint2* Bsm = (uint2*)(smem + S_B);               // [2][1024]
    float* xfsm = (float*)(smem + S_XF);
    float* bpsm = (float*)(smem + S_BP);

    int tid = threadIdx.x, w = tid >> 5, lane = tid & 31;
    int g = lane >> 2, tig = lane & 3;
    int m0 = blockIdx.x * 128;
    if (tid < 128) xfsm[tid] = g_xfeat[m0 + tid];
    else if (tid < 192) bpsm[tid - 128] = bphi[tid - 128];

    float acc[8][4];
#pragma unroll
    for (int nt = 0; nt < 8; nt++)
#pragma unroll
        for (int i = 0; i < 4; i++) acc[nt][i] = 0.f;

    const int arow = (tid >> 4);
    const int acol = 4 * (tid & 15);
    const float* asrc = pim + (size_t)(m0 + arow) * DIN + acol;

    auto issue = [&](int c, int s) {
        float* Ad = Asm + s * (128 * ASTR);
#pragma unroll
        for (int i = 0; i < 8; i++)
            cpa16(Ad + (arow + 16 * i) * ASTR + acol, asrc + (size_t)16 * i * DIN + c * 64);
        const char* bs = (const char*)(g_Bfrag + (size_t)c * 1024) + tid * 32;
        char* bd = (char*)(Bsm + s * 1024) + tid * 32;
        cpa16(bd, bs); cpa16(bd + 16, bs + 16);
        CP_COMMIT();
    };

    issue(0, 0); issue(1, 1);

    for (int c = 0; c < NCH; c++) {
        const int s = c & 1;
        CP_WAIT1();
        __syncthreads();
        const float* As = Asm + s * (128 * ASTR);
        const uint2* Bs = Bsm + s * 1024;
        const int r0 = 16 * w + g;
#pragma unroll
        for (int ks = 0; ks < 4; ks++) {
            const int kb = 16 * ks + 2 * tig;
            float2 f0 = *(const float2*)(As + r0 * ASTR + kb);
            float2 f1 = *(const float2*)(As + (r0 + 8) * ASTR + kb);
            float2 f2 = *(const float2*)(As + r0 * ASTR + kb + 8);
            float2 f3 = *(const float2*)(As + (r0 + 8) * ASTR + kb + 8);
            uint32_t Ah[4];
            Ah[0] = cvt_hi(f0.x, f0.y);
            Ah[1] = cvt_hi(f1.x, f1.y);
            Ah[2] = cvt_hi(f2.x, f2.y);
            Ah[3] = cvt_hi(f3.x, f3.y);
#pragma unroll
            for (int nt = 0; nt < 8; nt++) {
                uint2 b = Bs[(ks * 8 + nt) * 32 + lane];
                mma_bf16(acc[nt], Ah, b.x, b.y);
            }
        }
        __syncthreads();
        if (c + 2 < NCH) issue(c + 2, s);
        else CP_COMMIT();
    }

    // Epilogue: u = D + bphi; approx score = dot(xf,u)/max(||u||,1e-12)
    int bi = w >> 2;
    float ps0 = 0.f, pd0 = 0.f, ps1 = 0.f, pd1 = 0.f;
#pragma unroll
    for (int nt = 0; nt < 8; nt++) {
        int col = nt * 8 + 2 * tig;
        float b0 = bpsm[col], b1 = bpsm[col + 1];
        float x0 = xfsm[bi * 64 + col], x1 = xfsm[bi * 64 + col + 1];
        float u;
        u = acc[nt][0] + b0; ps0 += u * u; pd0 += u * x0;
        u = acc[nt][1] + b1; ps0 += u * u; pd0 += u * x1;
        u = acc[nt][2] + b0; ps1 += u * u; pd1 += u * x0;
        u = acc[nt][3] + b1; ps1 += u * u; pd1 += u * x1;
    }
#pragma unroll
    for (int o = 1; o < 4; o <<= 1) {
        ps0 += __shfl_xor_sync(0xffffffffu, ps0, o);
        pd0 += __shfl_xor_sync(0xffffffffu, pd0, o);
        ps1 += __shfl_xor_sync(0xffffffffu, ps1, o);
        pd1 += __shfl_xor_sync(0xffffffffu, pd1, o);
    }
    if (tig == 0) {
        int r = m0 + 16 * w + g;
        g_scores[r]     = pd0 / fmaxf(sqrtf(ps0), 1e-12f);
        g_scores[r + 8] = pd1 / fmaxf(sqrtf(ps1), 1e-12f);
    }
}

// ---------------- kernel C1: candidate selection ----------------
__global__ void __launch_bounds__(256) kernC1() {
    int warp = threadIdx.x >> 5, lane = threadIdx.x & 31;
    int b = blockIdx.x * 8 + warp;
    float s0 = g_scores[b * 64 + lane];
    float s1 = g_scores[b * 64 + 32 + lane];
    float m = fmaxf(s0, s1);
#pragma unroll
    for (int o = 16; o >= 1; o >>= 1) m = fmaxf(m, __shfl_xor_sync(0xffffffffu, m, o));
    float th = m - CAND_TH;
    g_exact[b * 64 + lane]      = -1e30f;
    g_exact[b * 64 + 32 + lane] = -1e30f;
    if (s0 >= th) { int pos = atomicAdd(&g_count, 1); g_list[pos] = b * 64 + lane; }
    if (s1 >= th) { int pos = atomicAdd(&g_count, 1); g_list[pos] = b * 64 + 32 + lane; }
}

// ---------------- kernel R: exact fp32 refinement, WphiT chunk-staged in smem ----------------
// 8 candidates per iteration; 256 threads: f=tid&63, group g=tid>>6 handles cands g, g+4.
__global__ void __launch_bounds__(256) kernR(const float* __restrict__ pim,
                                             const float* __restrict__ bphi) {
    __shared__ __align__(16) float psm[8][DIN];      // 24KB
    __shared__ __align__(16) float Wsm[2][64 * 64];  // 32KB (double-buffered WphiT chunks)
    __shared__ float redp[8][2], redd[8][2];
    __shared__ int lsm[8];
    int tid = threadIdx.x;
    int cnt = g_count;

    auto stageW = [&](int c, int s) {
        const char* src = (const char*)(g_WphiT + c * 64 * 64) + tid * 64;
        char* dst = (char*)&Wsm[s][0] + tid * 64;
#pragma unroll
        for (int i = 0; i < 4; i++) cpa16(dst + 16 * i, src + 16 * i);
        CP_COMMIT();
    };

    for (int base = blockIdx.x * 8; base < cnt; base += gridDim.x * 8) {
        int nc = min(8, cnt - base);
        __syncthreads();          // protect smem reuse from previous iteration
        if (tid < 8) lsm[tid] = (tid < nc) ? g_list[base + tid] : -1;
        __syncthreads();
        // stage p rows (coalesced, 32 threads per row) + kick off W pipeline
        stageW(0, 0); stageW(1, 1);
        int row = tid >> 5, lj = tid & 31;
        if (row < nc) {
            const float4* src = (const float4*)(pim + (size_t)lsm[row] * DIN);
            float4* dst = (float4*)&psm[row][0];
#pragma unroll
            for (int jj = 0; jj < 6; jj++) dst[lj + 32 * jj] = src[lj + 32 * jj];
        }

        int f = tid & 63, g = tid >> 6;
        float u0 = 0.f, u1 = 0.f;
        for (int c = 0; c < NCH; c++) {
            const int s = c & 1;
            CP_WAIT1();
            __syncthreads();      // W chunk visible + psm visible (first iter)
            const float* Ws = &Wsm[s][0];
            const float* p0 = &psm[g][c * 64];
            const float* p1 = &psm[g + 4][c * 64];
#pragma unroll
            for (int kk = 0; kk < 64; kk++) {
                float wv = Ws[kk * 64 + f];
                u0 += wv * p0[kk];
                u1 += wv * p1[kk];
            }
            __syncthreads();
            if (c + 2 < NCH) stageW(c + 2, s);
            else CP_COMMIT();
        }
        float bp = bphi[f];
        u0 += bp; u1 += bp;

        int bk0 = lsm[g], bk1 = lsm[g + 4];
        float xf0 = (bk0 >= 0) ? g_xfeat[(bk0 >> 6) * 64 + f] : 0.f;
        float xf1 = (bk1 >= 0) ? g_xfeat[(bk1 >> 6) * 64 + f] : 0.f;
        float ps0 = u0 * u0, pd0 = u0 * xf0;
        float ps1 = u1 * u1, pd1 = u1 * xf1;
#pragma unroll
        for (int o = 16; o >= 1; o >>= 1) {
            ps0 += __shfl_xor_sync(0xffffffffu, ps0, o);
            pd0 += __shfl_xor_sync(0xffffffffu, pd0, o);
            ps1 += __shfl_xor_sync(0xffffffffu, ps1, o);
            pd1 += __shfl_xor_sync(0xffffffffu, pd1, o);
        }
        if ((tid & 31) == 0) {
            int h = (tid >> 5) & 1;
            redp[g][h] = ps0;     redd[g][h] = pd0;
            redp[g + 4][h] = ps1; redd[g + 4][h] = pd1;
        }
        __syncthreads();
        if (tid < 8 && lsm[tid] >= 0) {
            float ps = redp[tid][0] + redp[tid][1];
            float pd = redd[tid][0] + redd[tid][1];
            g_exact[lsm[tid]] = pd / fmaxf(sqrtf(ps), 1e-12f);
        }
    }
}

// ---------------- kernel D: fused softmax (exact scores) + weighted sum + mix + blend ----------------
__global__ void __launch_bounds__(192) kernD(const float* __restrict__ x,
                                             const float* __restrict__ p,
                                             const float* __restrict__ Wg,
                                             const float* __restrict__ bgv,
                                             const float* __restrict__ Wo,
                                             const float* __restrict__ bov,
                                             const float* __restrict__ sig_scale,
                                             const float* __restrict__ sig_shift,
                                             float* __restrict__ out) {
    __shared__ __align__(16) float buf[DIN];
    __shared__ __align__(16) float wsm[64];
    __shared__ float swsm;
    int tid = threadIdx.x;
    int b = blockIdx.x;

    if (tid < 32) {
        int lane = tid;
        float s0 = g_exact[b * 64 + lane];
        float s1 = g_exact[b * 64 + 32 + lane];
        float t0 = s0 * SHARPNESS, t1 = s1 * SHARPNESS;
        float mraw = fmaxf(s0, s1), mt = fmaxf(t0, t1);
#pragma unroll
        for (int o = 16; o >= 1; o >>= 1) {
            mraw = fmaxf(mraw, __shfl_xor_sync(0xffffffffu, mraw, o));
            mt   = fmaxf(mt,   __shfl_xor_sync(0xffffffffu, mt, o));
        }
        float e0 = expf(t0 - mt), e1 = expf(t1 - mt);
        float sum = e0 + e1;
#pragma unroll
        for (int o = 16; o >= 1; o >>= 1) sum += __shfl_xor_sync(0xffffffffu, sum, o);
        float inv = 1.f / sum;
        wsm[lane]      = e0 * inv;
        wsm[lane + 32] = e1 * inv;
        if (lane == 0) {
            float z = mraw * sig_scale[0] + sig_shift[0];
            swsm = 1.f / (1.f + expf(-z));
        }
    }
    __syncthreads();

    float4 acc = make_float4(0.f, 0.f, 0.f, 0.f);
    const float4* pb = (const float4*)(p + (size_t)b * KK * DIN);
    for (int k = 0; k < 64; k++) {
        float w = wsm[k];
        if (w > 1e-10f) {
            float4 v = pb[k * 192 + tid];
            acc.x += w * v.x; acc.y += w * v.y; acc.z += w * v.z; acc.w += w * v.w;
        }
    }
    ((float4*)buf)[tid] = acc;
    __syncthreads();

    int o = tid / 64;
    int hw = (tid % 64) * 4;
    float gg0 = Wg[o * 3 + 0], gg1 = Wg[o * 3 + 1], gg2 = Wg[o * 3 + 2];
    float bgc = bgv[o];
    float t[4];
#pragma unroll
    for (int j = 0; j < 4; j++)
        t[j] = gg0 * buf[hw + j] + gg1 * buf[256 + hw + j] + gg2 * buf[512 + hw + j] + bgc;
    __syncthreads();
#pragma unroll
    for (int j = 0; j < 4; j++) buf[o * 256 + hw + j] = t[j];
    __syncthreads();

    float oo0 = Wo[o * 3 + 0], oo1 = Wo[o * 3 + 1], oo2 = Wo[o * 3 + 2];
    float boc = bov[o];
    float sw = swsm;
    float4 xv = ((const float4*)(x + (size_t)b * DIN))[tid];
    float pa0 = oo0 * buf[hw + 0] + oo1 * buf[256 + hw + 0] + oo2 * buf[512 + hw + 0] + boc;
    float pa1 = oo0 * buf[hw + 1] + oo1 * buf[256 + hw + 1] + oo2 * buf[512 + hw + 1] + boc;
    float pa2 = oo0 * buf[hw + 2] + oo1 * buf[256 + hw + 2] + oo2 * buf[512 + hw + 2] + boc;
    float pa3 = oo0 * buf[hw + 3] + oo1 * buf[256 + hw + 3] + oo2 * buf[512 + hw + 3] + boc;
    float4 ov;
    ov.x = xv.x * (1.f - sw) + pa0 * sw;
    ov.y = xv.y * (1.f - sw) + pa1 * sw;
    ov.z = xv.z * (1.f - sw) + pa2 * sw;
    ov.w = xv.w * (1.f - sw) + pa3 * sw;
    ((float4*)(out + (size_t)b * DIN))[tid] = ov;
}

// ---------------- launch ----------------
extern "C" void kernel_launch(void* const* d_in, const int* in_sizes, int n_in,
                              void* d_out, int out_size) {
    const float* x         = (const float*)d_in[0];
    const float* p         = (const float*)d_in[1];
    const float* x_im      = (const float*)d_in[2];
    const float* p_im      = (const float*)d_in[3];
    const float* Wtheta    = (const float*)d_in[4];
    const float* btheta    = (const float*)d_in[5];
    const float* Wphi      = (const float*)d_in[6];
    const float* bphi      = (const float*)d_in[7];
    const float* Wg        = (const float*)d_in[8];
    const float* bg        = (const float*)d_in[9];
    const float* Wo        = (const float*)d_in[10];
    const float* bo        = (const float*)d_in[11];
    const float* sig_scale = (const float*)d_in[12];
    const float* sig_shift = (const float*)d_in[13];
    float* out = (float*)d_out;

    cudaFuncSetAttribute(kernB, cudaFuncAttributeMaxDynamicSharedMemorySize, SMEMB_TOTAL);

    kernE<<<48, 256>>>(Wphi);
    kernE2<<<192, 256>>>(Wphi);
    kernA<<<BB / 8, 256>>>(x_im, Wtheta, btheta);
    kernB<<<MROWS / 128, 256, SMEMB_TOTAL>>>(p_im, bphi);
    kernC1<<<BB / 8, 256>>>();
    kernR<<<512, 256>>>(p_im, bphi);
    kernD<<<BB, 192>>>(x, p, Wg, bg, Wo, bo, sig_scale, sig_shift, out);
}

// round 14
// speedup vs baseline: 1.3666x; 1.0917x over previous
#include <cuda_runtime.h>
#include <cuda_bf16.h>
#include <math.h>
#include <stdint.h>

// Problem constants
#define BB 2048
#define KK 64
#define DIN 768
#define CF 64
#define MROWS (BB*KK)
#define SHARPNESS 1048576.0f
#define NCH 12            // K chunks of 64
#define CAND_TH 0.03f     // approx-score gap threshold for refinement

// ---------------- scratch ----------------
__device__ float g_xfeat[BB*CF];
__device__ float g_exact[MROWS];         // exact scores for candidates, -1e30 else
__device__ int   g_list[MROWS];          // candidate list (b*64+k)
__device__ int   g_count;
__device__ float g_WphiT[DIN*CF];        // Wphi transposed [k][f], fp32
// Fragment-ordered bf16 HI images of Wphi: [c][ks][nt][lane] uint2 {h01,h23}
__device__ __align__(16) uint2 g_Bfrag[NCH*4*8*32];   // 98KB, L2-resident

// ---------------- helpers ----------------
__device__ __forceinline__ void cpa16(void* smem, const void* g) {
    unsigned s = (unsigned)__cvta_generic_to_shared(smem);
    asm volatile("cp.async.cg.shared.global [%0], [%1], 16;" :: "r"(s), "l"(g));
}
#define CP_COMMIT() asm volatile("cp.async.commit_group;")
#define CP_WAIT1()  asm volatile("cp.async.wait_group 1;" ::: "memory")

__device__ __forceinline__ uint32_t cvt_hi(float a0, float a1) {
    uint32_t hp;
    asm("cvt.rn.satfinite.bf16x2.f32 %0, %1, %2;" : "=r"(hp) : "f"(a1), "f"(a0));
    return hp;
}

__device__ __forceinline__ void mma_bf16(float* d, const uint32_t* a, uint32_t b0, uint32_t b1) {
    asm volatile("mma.sync.aligned.m16n8k16.row.col.f32.bf16.bf16.f32 "
        "{%0,%1,%2,%3}, {%4,%5,%6,%7}, {%8,%9}, {%0,%1,%2,%3};"
        : "+f"(d[0]), "+f"(d[1]), "+f"(d[2]), "+f"(d[3])
        : "r"(a[0]), "r"(a[1]), "r"(a[2]), "r"(a[3]), "r"(b0), "r"(b1));
}

// ---------------- kernel EF: fused Wphi preprocessing ----------------
// blocks [0,48): bf16 fragment images; blocks [48,240): fp32 WphiT (+count reset)
__global__ void kernEF(const float* __restrict__ Wphi) {
    int bid = blockIdx.x, tid = threadIdx.x;
    if (bid < 48) {
        int idx = bid * 256 + tid;               // < 12288
        int lane = idx & 31;
        int t = idx >> 5;
        int nt = t & 7, ks = (t >> 3) & 3, c = t >> 5;
        int g = lane >> 2, tig = lane & 3;
        int n = nt * 8 + g;
        int k0 = c * 64 + ks * 16 + 2 * tig;
        const float* wr = Wphi + n * DIN + k0;
        uint32_t h01 = cvt_hi(wr[0], wr[1]);
        uint32_t h23 = cvt_hi(wr[8], wr[9]);
        g_Bfrag[((c * 4 + ks) * 8 + nt) * 32 + lane] = make_uint2(h01, h23);
    } else {
        int o = (bid - 48) * 256 + tid;          // o = k*64+f, < 49152
        if (o == 0) g_count = 0;
        int k = o >> 6, f = o & 63;
        g_WphiT[o] = Wphi[f * DIN + k];
    }
}

// ---------------- kernel A: x_feat, Wtheta chunk-staged, 16 b/block ----------------
// 256 threads: f = tid&63, q = tid>>6; thread handles batches 4q..4q+3.
__global__ void __launch_bounds__(256) kernA(const float* __restrict__ xim,
                                             const float* __restrict__ Wtheta,
                                             const float* __restrict__ btheta) {
    __shared__ __align__(16) float xt[DIN * 16];     // transposed [k][b], 48KB
    __shared__ __align__(16) float Wsm[2][64 * 64];  // WphiT-style [k][f] chunks, 32KB
    __shared__ float wred[16][2];
    int tid = threadIdx.x;
    int b0 = blockIdx.x * 16;

    auto stageW = [&](int c, int s) {
        // Wtheta is [f][768]; we need chunk c as [kk][f]. Gather per element (L2-hot).
        // 4096 elems / 256 thr = 16 each; scalar stores (transpose) — cheap vs GEMV.
        for (int i = 0; i < 16; i++) {
            int e = tid + 256 * i;               // e = kk*64+f
            int kk = e >> 6, f = e & 63;
            Wsm[s][e] = Wtheta[f * DIN + c * 64 + kk];
        }
    };

    // load + transpose x_im: 16 rows x 768
    {
        const float4* src = (const float4*)(xim + (size_t)b0 * DIN);
        for (int i = 0; i < 12; i++) {
            int e = tid + 256 * i;               // e over 3072 float4s
            int row = e / 192, col4 = e % 192;   // col4*4 = k base
            float4 v = src[row * 192 + col4];
            int k = col4 * 4;
            xt[(k + 0) * 16 + row] = v.x;
            xt[(k + 1) * 16 + row] = v.y;
            xt[(k + 2) * 16 + row] = v.z;
            xt[(k + 3) * 16 + row] = v.w;
        }
    }
    stageW(0, 0);
    __syncthreads();

    int f = tid & 63, q = tid >> 6;
    float acc[4] = {0.f, 0.f, 0.f, 0.f};
    for (int c = 0; c < NCH; c++) {
        const int s = c & 1;
        // stage next chunk AFTER current sync (simple ping-pong; W gather is L2-hot)
#pragma unroll 4
        for (int kk = 0; kk < 64; kk++) {
            float wv = Wsm[s][kk * 64 + f];
            const float4 xv = *(const float4*)&xt[(c * 64 + kk) * 16 + 4 * q];
            acc[0] += wv * xv.x; acc[1] += wv * xv.y;
            acc[2] += wv * xv.z; acc[3] += wv * xv.w;
        }
        __syncthreads();
        if (c + 1 < NCH) { stageW(c + 1, (c + 1) & 1); }
        __syncthreads();
    }
    float bt = btheta[f];
#pragma unroll
    for (int j = 0; j < 4; j++) acc[j] += bt;

    // l2norm per batch: 64 threads (2 warps) per batch-quad share q
#pragma unroll
    for (int j = 0; j < 4; j++) {
        float ss = acc[j] * acc[j];
#pragma unroll
        for (int o = 1; o < 32; o <<= 1) ss += __shfl_xor_sync(0xffffffffu, ss, o);
        int w = tid >> 5;
        if ((tid & 31) == 0) wred[q * 4 + j][w & 1] = ss;
        __syncthreads();
        float n = wred[q * 4 + j][0] + wred[q * 4 + j][1];
        g_xfeat[(b0 + 4 * q + j) * CF + f] = acc[j] / fmaxf(sqrtf(n), 1e-12f);
        __syncthreads();
    }
}

// ---------------- kernel B: 1-term bf16 HMMA + score epilogue + candidate selection ----------------
#define ASTR 68                 // fp32 row stride in smem (272B = 17x16B)
#define S_A  0                  // 2 stages x 128*68*4 = 69632
#define S_B  69632              // 2 stages x 8KB = 16384
#define S_XF 86016              // 512
#define S_BP 86528              // 256
#define S_SC 86784              // 512 (per-row scores for selection)
#define SMEMB_TOTAL 87296

__global__ void __launch_bounds__(256, 2) kernB(const float* __restrict__ pim,
                                                const float* __restrict__ bphi) {
    extern __shared__ __align__(16) char smem[];
    float* Asm = (float*)(smem + S_A);               // [2][128*ASTR]
    uint2* Bsm = (uint2*)(smem + S_B);               // [2][1024]
    float* xfsm = (float*)(smem + S_XF);
    float* bpsm = (float*)(smem + S_BP);
    float* scsm = (float*)(smem + S_SC);             // [128]

    int tid = threadIdx.x, w = tid >> 5, lane = tid & 31;
    int g = lane >> 2, tig = lane & 3;
    int m0 = blockIdx.x * 128;
    if (tid < 128) xfsm[tid] = g_xfeat[m0 + tid];
    else if (tid < 192) bpsm[tid - 128] = bphi[tid - 128];

    float acc[8][4];
#pragma unroll
    for (int nt = 0; nt < 8; nt++)
#pragma unroll
        for (int i = 0; i < 4; i++) acc[nt][i] = 0.f;

    const int arow = (tid >> 4);
    const int acol = 4 * (tid & 15);
    const float* asrc = pim + (size_t)(m0 + arow) * DIN + acol;

    auto issue = [&](int c, int s) {
        float* Ad = Asm + s * (128 * ASTR);
#pragma unroll
        for (int i = 0; i < 8; i++)
            cpa16(Ad + (arow + 16 * i) * ASTR + acol, asrc + (size_t)16 * i * DIN + c * 64);
        const char* bs = (const char*)(g_Bfrag + (size_t)c * 1024) + tid * 32;
        char* bd = (char*)(Bsm + s * 1024) + tid * 32;
        cpa16(bd, bs); cpa16(bd + 16, bs + 16);
        CP_COMMIT();
    };

    issue(0, 0); issue(1, 1);

    for (int c = 0; c < NCH; c++) {
        const int s = c & 1;
        CP_WAIT1();
        __syncthreads();
        const float* As = Asm + s * (128 * ASTR);
        const uint2* Bs = Bsm + s * 1024;
        const int r0 = 16 * w + g;
#pragma unroll
        for (int ks = 0; ks < 4; ks++) {
            const int kb = 16 * ks + 2 * tig;
            float2 f0 = *(const float2*)(As + r0 * ASTR + kb);
            float2 f1 = *(const float2*)(As + (r0 + 8) * ASTR + kb);
            float2 f2 = *(const float2*)(As + r0 * ASTR + kb + 8);
            float2 f3 = *(const float2*)(As + (r0 + 8) * ASTR + kb + 8);
            uint32_t Ah[4];
            Ah[0] = cvt_hi(f0.x, f0.y);
            Ah[1] = cvt_hi(f1.x, f1.y);
            Ah[2] = cvt_hi(f2.x, f2.y);
            Ah[3] = cvt_hi(f3.x, f3.y);
#pragma unroll
            for (int nt = 0; nt < 8; nt++) {
                uint2 b = Bs[(ks * 8 + nt) * 32 + lane];
                mma_bf16(acc[nt], Ah, b.x, b.y);
            }
        }
        __syncthreads();
        if (c + 2 < NCH) issue(c + 2, s);
        else CP_COMMIT();
    }

    // Epilogue: u = D + bphi; approx score = dot(xf,u)/max(||u||,1e-12)
    int bi = w >> 2;
    float ps0 = 0.f, pd0 = 0.f, ps1 = 0.f, pd1 = 0.f;
#pragma unroll
    for (int nt = 0; nt < 8; nt++) {
        int col = nt * 8 + 2 * tig;
        float b0 = bpsm[col], b1 = bpsm[col + 1];
        float x0 = xfsm[bi * 64 + col], x1 = xfsm[bi * 64 + col + 1];
        float u;
        u = acc[nt][0] + b0; ps0 += u * u; pd0 += u * x0;
        u = acc[nt][1] + b1; ps0 += u * u; pd0 += u * x1;
        u = acc[nt][2] + b0; ps1 += u * u; pd1 += u * x0;
        u = acc[nt][3] + b1; ps1 += u * u; pd1 += u * x1;
    }
#pragma unroll
    for (int o = 1; o < 4; o <<= 1) {
        ps0 += __shfl_xor_sync(0xffffffffu, ps0, o);
        pd0 += __shfl_xor_sync(0xffffffffu, pd0, o);
        ps1 += __shfl_xor_sync(0xffffffffu, ps1, o);
        pd1 += __shfl_xor_sync(0xffffffffu, pd1, o);
    }
    int lr = 16 * w + g;
    if (tig == 0) {
        scsm[lr]     = pd0 / fmaxf(sqrtf(ps0), 1e-12f);
        scsm[lr + 8] = pd1 / fmaxf(sqrtf(ps1), 1e-12f);
    }
    if (tid < 128) g_exact[m0 + tid] = -1e30f;
    __syncthreads();

    // Candidate selection: warp 0 -> b half 0, warp 1 -> b half 1
    if (w < 2) {
        float s0 = scsm[w * 64 + lane];
        float s1 = scsm[w * 64 + 32 + lane];
        float m = fmaxf(s0, s1);
#pragma unroll
        for (int o = 16; o >= 1; o >>= 1) m = fmaxf(m, __shfl_xor_sync(0xffffffffu, m, o));
        float th = m - CAND_TH;
        int bidx = m0 + w * 64;      // == (2*blockIdx.x + w)*64
        if (s0 >= th) { int pos = atomicAdd(&g_count, 1); g_list[pos] = bidx + lane; }
        if (s1 >= th) { int pos = atomicAdd(&g_count, 1); g_list[pos] = bidx + 32 + lane; }
    }
}

// ---------------- kernel R: exact fp32 refinement, WphiT chunk-staged in smem ----------------
__global__ void __launch_bounds__(256) kernR(const float* __restrict__ pim,
                                             const float* __restrict__ bphi) {
    __shared__ __align__(16) float psm[8][DIN];      // 24KB
    __shared__ __align__(16) float Wsm[2][64 * 64];  // 32KB
    __shared__ float redp[8][2], redd[8][2];
    __shared__ int lsm[8];
    int tid = threadIdx.x;
    int cnt = g_count;

    auto stageW = [&](int c, int s) {
        const char* src = (const char*)(g_WphiT + c * 64 * 64) + tid * 64;
        char* dst = (char*)&Wsm[s][0] + tid * 64;
#pragma unroll
        for (int i = 0; i < 4; i++) cpa16(dst + 16 * i, src + 16 * i);
        CP_COMMIT();
    };

    for (int base = blockIdx.x * 8; base < cnt; base += gridDim.x * 8) {
        int nc = min(8, cnt - base);
        __syncthreads();
        if (tid < 8) lsm[tid] = (tid < nc) ? g_list[base + tid] : -1;
        __syncthreads();
        stageW(0, 0); stageW(1, 1);
        int row = tid >> 5, lj = tid & 31;
        if (row < nc) {
            const float4* src = (const float4*)(pim + (size_t)lsm[row] * DIN);
            float4* dst = (float4*)&psm[row][0];
#pragma unroll
            for (int jj = 0; jj < 6; jj++) dst[lj + 32 * jj] = src[lj + 32 * jj];
        }

        int f = tid & 63, g = tid >> 6;
        float u0 = 0.f, u1 = 0.f;
        for (int c = 0; c < NCH; c++) {
            const int s = c & 1;
            CP_WAIT1();
            __syncthreads();
            const float* Ws = &Wsm[s][0];
            const float* p0 = &psm[g][c * 64];
            const float* p1 = &psm[g + 4][c * 64];
#pragma unroll
            for (int kk = 0; kk < 64; kk++) {
                float wv = Ws[kk * 64 + f];
                u0 += wv * p0[kk];
                u1 += wv * p1[kk];
            }
            __syncthreads();
            if (c + 2 < NCH) stageW(c + 2, s);
            else CP_COMMIT();
        }
        float bp = bphi[f];
        u0 += bp; u1 += bp;

        int bk0 = lsm[g], bk1 = lsm[g + 4];
        float xf0 = (bk0 >= 0) ? g_xfeat[(bk0 >> 6) * 64 + f] : 0.f;
        float xf1 = (bk1 >= 0) ? g_xfeat[(bk1 >> 6) * 64 + f] : 0.f;
        float ps0 = u0 * u0, pd0 = u0 * xf0;
        float ps1 = u1 * u1, pd1 = u1 * xf1;
#pragma unroll
        for (int o = 16; o >= 1; o >>= 1) {
            ps0 += __shfl_xor_sync(0xffffffffu, ps0, o);
            pd0 += __shfl_xor_sync(0xffffffffu, pd0, o);
            ps1 += __shfl_xor_sync(0xffffffffu, ps1, o);
            pd1 += __shfl_xor_sync(0xffffffffu, pd1, o);
        }
        if ((tid & 31) == 0) {
            int h = (tid >> 5) & 1;
            redp[g][h] = ps0;     redd[g][h] = pd0;
            redp[g + 4][h] = ps1; redd[g + 4][h] = pd1;
        }
        __syncthreads();
        if (tid < 8 && lsm[tid] >= 0) {
            float ps = redp[tid][0] + redp[tid][1];
            float pd = redd[tid][0] + redd[tid][1];
            g_exact[lsm[tid]] = pd / fmaxf(sqrtf(ps), 1e-12f);
        }
    }
}

// ---------------- kernel D: softmax + ACTIVE-LIST weighted sum + mix + blend ----------------
__global__ void __launch_bounds__(192) kernD(const float* __restrict__ x,
                                             const float* __restrict__ p,
                                             const float* __restrict__ Wg,
                                             const float* __restrict__ bgv,
                                             const float* __restrict__ Wo,
                                             const float* __restrict__ bov,
                                             const float* __restrict__ sig_scale,
                                             const float* __restrict__ sig_shift,
                                             float* __restrict__ out) {
    __shared__ __align__(16) float buf[DIN];
    __shared__ __align__(16) float wsm[64];
    __shared__ int actsm[64];
    __shared__ float swsm;
    __shared__ int nactsm;
    int tid = threadIdx.x;
    int b = blockIdx.x;

    if (tid < 32) {
        int lane = tid;
        float s0 = g_exact[b * 64 + lane];
        float s1 = g_exact[b * 64 + 32 + lane];
        float t0 = s0 * SHARPNESS, t1 = s1 * SHARPNESS;
        float mraw = fmaxf(s0, s1), mt = fmaxf(t0, t1);
#pragma unroll
        for (int o = 16; o >= 1; o >>= 1) {
            mraw = fmaxf(mraw, __shfl_xor_sync(0xffffffffu, mraw, o));
            mt   = fmaxf(mt,   __shfl_xor_sync(0xffffffffu, mt, o));
        }
        float e0 = expf(t0 - mt), e1 = expf(t1 - mt);
        float sum = e0 + e1;
#pragma unroll
        for (int o = 16; o >= 1; o >>= 1) sum += __shfl_xor_sync(0xffffffffu, sum, o);
        float inv = 1.f / sum;
        float w0 = e0 * inv, w1 = e1 * inv;
        wsm[lane]      = w0;
        wsm[lane + 32] = w1;
        // compact active list (w > 1e-10, same threshold as the old inner-loop guard)
        uint32_t bal0 = __ballot_sync(0xffffffffu, w0 > 1e-10f);
        uint32_t bal1 = __ballot_sync(0xffffffffu, w1 > 1e-10f);
        int c0 = __popc(bal0);
        if (w0 > 1e-10f) actsm[__popc(bal0 & ((1u << lane) - 1u))] = lane;
        if (w1 > 1e-10f) actsm[c0 + __popc(bal1 & ((1u << lane) - 1u))] = lane + 32;
        if (lane == 0) {
            nactsm = c0 + __popc(bal1);
            float z = mraw * sig_scale[0] + sig_shift[0];
            swsm = 1.f / (1.f + expf(-z));
        }
    }
    __syncthreads();

    int nact = nactsm;
    float4 acc = make_float4(0.f, 0.f, 0.f, 0.f);
    const float4* pb = (const float4*)(p + (size_t)b * KK * DIN);
    for (int j = 0; j < nact; j++) {
        int k = actsm[j];
        float w = wsm[k];
        float4 v = pb[k * 192 + tid];
        acc.x += w * v.x; acc.y += w * v.y; acc.z += w * v.z; acc.w += w * v.w;
    }
    ((float4*)buf)[tid] = acc;
    __syncthreads();

    int o = tid / 64;
    int hw = (tid % 64) * 4;
    float gg0 = Wg[o * 3 + 0], gg1 = Wg[o * 3 + 1], gg2 = Wg[o * 3 + 2];
    float bgc = bgv[o];
    float t[4];
#pragma unroll
    for (int j = 0; j < 4; j++)
        t[j] = gg0 * buf[hw + j] + gg1 * buf[256 + hw + j] + gg2 * buf[512 + hw + j] + bgc;
    __syncthreads();
#pragma unroll
    for (int j = 0; j < 4; j++) buf[o * 256 + hw + j] = t[j];
    __syncthreads();

    float oo0 = Wo[o * 3 + 0], oo1 = Wo[o * 3 + 1], oo2 = Wo[o * 3 + 2];
    float boc = bov[o];
    float sw = swsm;
    float4 xv = ((const float4*)(x + (size_t)b * DIN))[tid];
    float pa0 = oo0 * buf[hw + 0] + oo1 * buf[256 + hw + 0] + oo2 * buf[512 + hw + 0] + boc;
    float pa1 = oo0 * buf[hw + 1] + oo1 * buf[256 + hw + 1] + oo2 * buf[512 + hw + 1] + boc;
    float pa2 = oo0 * buf[hw + 2] + oo1 * buf[256 + hw + 2] + oo2 * buf[512 + hw + 2] + boc;
    float pa3 = oo0 * buf[hw + 3] + oo1 * buf[256 + hw + 3] + oo2 * buf[512 + hw + 3] + boc;
    float4 ov;
    ov.x = xv.x * (1.f - sw) + pa0 * sw;
    ov.y = xv.y * (1.f - sw) + pa1 * sw;
    ov.z = xv.z * (1.f - sw) + pa2 * sw;
    ov.w = xv.w * (1.f - sw) + pa3 * sw;
    ((float4*)(out + (size_t)b * DIN))[tid] = ov;
}

// ---------------- launch ----------------
extern "C" void kernel_launch(void* const* d_in, const int* in_sizes, int n_in,
                              void* d_out, int out_size) {
    const float* x         = (const float*)d_in[0];
    const float* p         = (const float*)d_in[1];
    const float* x_im      = (const float*)d_in[2];
    const float* p_im      = (const float*)d_in[3];
    const float* Wtheta    = (const float*)d_in[4];
    const float* btheta    = (const float*)d_in[5];
    const float* Wphi      = (const float*)d_in[6];
    const float* bphi      = (const float*)d_in[7];
    const float* Wg        = (const float*)d_in[8];
    const float* bg        = (const float*)d_in[9];
    const float* Wo        = (const float*)d_in[10];
    const float* bo        = (const float*)d_in[11];
    const float* sig_scale = (const float*)d_in[12];
    const float* sig_shift = (const float*)d_in[13];
    float* out = (float*)d_out;

    cudaFuncSetAttribute(kernB, cudaFuncAttributeMaxDynamicSharedMemorySize, SMEMB_TOTAL);

    kernEF<<<240, 256>>>(Wphi);
    kernA<<<BB / 16, 256>>>(x_im, Wtheta, btheta);
    kernB<<<MROWS / 128, 256, SMEMB_TOTAL>>>(p_im, bphi);
    kernR<<<512, 256>>>(p_im, bphi);
    kernD<<<BB, 192>>>(x, p, Wg, bg, Wo, bo, sig_scale, sig_shift, out);
}

// round 15
// speedup vs baseline: 1.6693x; 1.2215x over previous
#include <cuda_runtime.h>
#include <cuda_bf16.h>
#include <math.h>
#include <stdint.h>

// Problem constants
#define BB 2048
#define KK 64
#define DIN 768
#define CF 64
#define MROWS (BB*KK)
#define SHARPNESS 1048576.0f
#define NCH 12            // K chunks of 64
#define CAND_TH 0.03f     // approx-score gap threshold for refinement

// ---------------- scratch ----------------
__device__ float g_xfeat[BB*CF];
__device__ float g_exact[MROWS];         // exact scores for candidates, -1e30 else
__device__ int   g_list[MROWS];          // candidate list (b*64+k)
__device__ int   g_count;
__device__ float g_WphiT[DIN*CF];        // Wphi transposed [k][f], fp32
__device__ float g_WthetaT[DIN*CF];      // Wtheta transposed [k][f], fp32
// Fragment-ordered bf16 HI images of Wphi: [c][ks][nt][lane] uint2 {h01,h23}
__device__ __align__(16) uint2 g_Bfrag[NCH*4*8*32];   // 98KB, L2-resident

// ---------------- helpers ----------------
__device__ __forceinline__ void cpa16(void* smem, const void* g) {
    unsigned s = (unsigned)__cvta_generic_to_shared(smem);
    asm volatile("cp.async.cg.shared.global [%0], [%1], 16;" :: "r"(s), "l"(g));
}
#define CP_COMMIT() asm volatile("cp.async.commit_group;")
#define CP_WAIT1()  asm volatile("cp.async.wait_group 1;" ::: "memory")

__device__ __forceinline__ uint32_t cvt_hi(float a0, float a1) {
    uint32_t hp;
    asm("cvt.rn.satfinite.bf16x2.f32 %0, %1, %2;" : "=r"(hp) : "f"(a1), "f"(a0));
    return hp;
}

__device__ __forceinline__ void mma_bf16(float* d, const uint32_t* a, uint32_t b0, uint32_t b1) {
    asm volatile("mma.sync.aligned.m16n8k16.row.col.f32.bf16.bf16.f32 "
        "{%0,%1,%2,%3}, {%4,%5,%6,%7}, {%8,%9}, {%0,%1,%2,%3};"
        : "+f"(d[0]), "+f"(d[1]), "+f"(d[2]), "+f"(d[3])
        : "r"(a[0]), "r"(a[1]), "r"(a[2]), "r"(a[3]), "r"(b0), "r"(b1));
}

// ---------------- kernel EF: fused weight preprocessing ----------------
// [0,48): Wphi bf16 fragments; [48,240): WphiT fp32 (+count reset); [240,432): WthetaT fp32
__global__ void kernEF(const float* __restrict__ Wphi, const float* __restrict__ Wtheta) {
    int bid = blockIdx.x, tid = threadIdx.x;
    if (bid < 48) {
        int idx = bid * 256 + tid;
        int lane = idx & 31;
        int t = idx >> 5;
        int nt = t & 7, ks = (t >> 3) & 3, c = t >> 5;
        int g = lane >> 2, tig = lane & 3;
        int n = nt * 8 + g;
        int k0 = c * 64 + ks * 16 + 2 * tig;
        const float* wr = Wphi + n * DIN + k0;
        uint32_t h01 = cvt_hi(wr[0], wr[1]);
        uint32_t h23 = cvt_hi(wr[8], wr[9]);
        g_Bfrag[((c * 4 + ks) * 8 + nt) * 32 + lane] = make_uint2(h01, h23);
    } else if (bid < 240) {
        int o = (bid - 48) * 256 + tid;          // o = k*64+f
        if (o == 0) g_count = 0;
        int k = o >> 6, f = o & 63;
        g_WphiT[o] = Wphi[f * DIN + k];
    } else {
        int o = (bid - 240) * 256 + tid;
        int k = o >> 6, f = o & 63;
        g_WthetaT[o] = Wtheta[f * DIN + k];
    }
}

// ---------------- kernel A: x_feat, WthetaT chunk-staged via cp.async, 16 b/block ----------------
// 256 threads: f = tid&63, q = tid>>6 handles batches 4q..4q+3.
__global__ void __launch_bounds__(256) kernA(const float* __restrict__ xim,
                                             const float* __restrict__ btheta) {
    __shared__ __align__(16) float xs[16 * DIN];     // row-major, 48KB
    __shared__ __align__(16) float Wsm[2][64 * 64];  // [kk][f] chunks, 32KB
    __shared__ float wred[16][2];
    int tid = threadIdx.x;
    int b0 = blockIdx.x * 16;

    auto stageW = [&](int c, int s) {
        const char* src = (const char*)(g_WthetaT + c * 4096) + tid * 64;
        char* dst = (char*)&Wsm[s][0] + tid * 64;
#pragma unroll
        for (int i = 0; i < 4; i++) cpa16(dst + 16 * i, src + 16 * i);
        CP_COMMIT();
    };

    stageW(0, 0); stageW(1, 1);
    {   // stage x rows (coalesced float4; reads later are broadcast -> conflict-free)
        const float4* src = (const float4*)(xim + (size_t)b0 * DIN);
        float4* d4 = (float4*)xs;
#pragma unroll
        for (int j = 0; j < 12; j++) d4[tid + 256 * j] = src[tid + 256 * j];
    }

    int f = tid & 63, q = tid >> 6;
    float acc[4] = {0.f, 0.f, 0.f, 0.f};
    for (int c = 0; c < NCH; c++) {
        const int s = c & 1;
        CP_WAIT1();
        __syncthreads();
        const float* Ws = &Wsm[s][0];
#pragma unroll 8
        for (int kk = 0; kk < 64; kk += 2) {
            float w0 = Ws[kk * 64 + f];
            float w1 = Ws[(kk + 1) * 64 + f];
#pragma unroll
            for (int j = 0; j < 4; j++) {
                float2 xv = *(const float2*)&xs[(4 * q + j) * DIN + c * 64 + kk];
                acc[j] += w0 * xv.x;
                acc[j] += w1 * xv.y;
            }
        }
        __syncthreads();
        if (c + 2 < NCH) stageW(c + 2, s);
        else CP_COMMIT();
    }
    float bt = btheta[f];
#pragma unroll
    for (int j = 0; j < 4; j++) acc[j] += bt;

    // l2norm: reduce over 64 threads (2 warps) sharing q
    int w = tid >> 5;
    float ss[4];
#pragma unroll
    for (int j = 0; j < 4; j++) {
        ss[j] = acc[j] * acc[j];
#pragma unroll
        for (int o = 1; o < 32; o <<= 1) ss[j] += __shfl_xor_sync(0xffffffffu, ss[j], o);
    }
    if ((tid & 31) == 0) {
#pragma unroll
        for (int j = 0; j < 4; j++) wred[q * 4 + j][w & 1] = ss[j];
    }
    __syncthreads();
#pragma unroll
    for (int j = 0; j < 4; j++) {
        float n = wred[q * 4 + j][0] + wred[q * 4 + j][1];
        g_xfeat[(b0 + 4 * q + j) * CF + f] = acc[j] / fmaxf(sqrtf(n), 1e-12f);
    }
}

// ---------------- kernel B: 1-term bf16 HMMA + score epilogue + candidate selection ----------------
#define ASTR 68
#define S_A  0                  // 2 stages x 128*68*4 = 69632
#define S_B  69632              // 2 stages x 8KB = 16384
#define S_XF 86016              // 512
#define S_BP 86528              // 256
#define S_SC 86784              // 512
#define SMEMB_TOTAL 87296

__global__ void __launch_bounds__(256, 2) kernB(const float* __restrict__ pim,
                                                const float* __restrict__ bphi) {
    extern __shared__ __align__(16) char smem[];
    float* Asm = (float*)(smem + S_A);
    uint2* Bsm = (uint2*)(smem + S_B);
    float* xfsm = (float*)(smem + S_XF);
    float* bpsm = (float*)(smem + S_BP);
    float* scsm = (float*)(smem + S_SC);

    int tid = threadIdx.x, w = tid >> 5, lane = tid & 31;
    int g = lane >> 2, tig = lane & 3;
    int m0 = blockIdx.x * 128;
    if (tid < 128) xfsm[tid] = g_xfeat[m0 + tid];
    else if (tid < 192) bpsm[tid - 128] = bphi[tid - 128];

    float acc[8][4];
#pragma unroll
    for (int nt = 0; nt < 8; nt++)
#pragma unroll
        for (int i = 0; i < 4; i++) acc[nt][i] = 0.f;

    const int arow = (tid >> 4);
    const int acol = 4 * (tid & 15);
    const float* asrc = pim + (size_t)(m0 + arow) * DIN + acol;

    auto issue = [&](int c, int s) {
        float* Ad = Asm + s * (128 * ASTR);
#pragma unroll
        for (int i = 0; i < 8; i++)
            cpa16(Ad + (arow + 16 * i) * ASTR + acol, asrc + (size_t)16 * i * DIN + c * 64);
        const char* bs = (const char*)(g_Bfrag + (size_t)c * 1024) + tid * 32;
        char* bd = (char*)(Bsm + s * 1024) + tid * 32;
        cpa16(bd, bs); cpa16(bd + 16, bs + 16);
        CP_COMMIT();
    };

    issue(0, 0); issue(1, 1);

    for (int c = 0; c < NCH; c++) {
        const int s = c & 1;
        CP_WAIT1();
        __syncthreads();
        const float* As = Asm + s * (128 * ASTR);
        const uint2* Bs = Bsm + s * 1024;
        const int r0 = 16 * w + g;
#pragma unroll
        for (int ks = 0; ks < 4; ks++) {
            const int kb = 16 * ks + 2 * tig;
            float2 f0 = *(const float2*)(As + r0 * ASTR + kb);
            float2 f1 = *(const float2*)(As + (r0 + 8) * ASTR + kb);
            float2 f2 = *(const float2*)(As + r0 * ASTR + kb + 8);
            float2 f3 = *(const float2*)(As + (r0 + 8) * ASTR + kb + 8);
            uint32_t Ah[4];
            Ah[0] = cvt_hi(f0.x, f0.y);
            Ah[1] = cvt_hi(f1.x, f1.y);
            Ah[2] = cvt_hi(f2.x, f2.y);
            Ah[3] = cvt_hi(f3.x, f3.y);
#pragma unroll
            for (int nt = 0; nt < 8; nt++) {
                uint2 b = Bs[(ks * 8 + nt) * 32 + lane];
                mma_bf16(acc[nt], Ah, b.x, b.y);
            }
        }
        __syncthreads();
        if (c + 2 < NCH) issue(c + 2, s);
        else CP_COMMIT();
    }

    int bi = w >> 2;
    float ps0 = 0.f, pd0 = 0.f, ps1 = 0.f, pd1 = 0.f;
#pragma unroll
    for (int nt = 0; nt < 8; nt++) {
        int col = nt * 8 + 2 * tig;
        float b0 = bpsm[col], b1 = bpsm[col + 1];
        float x0 = xfsm[bi * 64 + col], x1 = xfsm[bi * 64 + col + 1];
        float u;
        u = acc[nt][0] + b0; ps0 += u * u; pd0 += u * x0;
        u = acc[nt][1] + b1; ps0 += u * u; pd0 += u * x1;
        u = acc[nt][2] + b0; ps1 += u * u; pd1 += u * x0;
        u = acc[nt][3] + b1; ps1 += u * u; pd1 += u * x1;
    }
#pragma unroll
    for (int o = 1; o < 4; o <<= 1) {
        ps0 += __shfl_xor_sync(0xffffffffu, ps0, o);
        pd0 += __shfl_xor_sync(0xffffffffu, pd0, o);
        ps1 += __shfl_xor_sync(0xffffffffu, ps1, o);
        pd1 += __shfl_xor_sync(0xffffffffu, pd1, o);
    }
    int lr = 16 * w + g;
    if (tig == 0) {
        scsm[lr]     = pd0 / fmaxf(sqrtf(ps0), 1e-12f);
        scsm[lr + 8] = pd1 / fmaxf(sqrtf(ps1), 1e-12f);
    }
    if (tid < 128) g_exact[m0 + tid] = -1e30f;
    __syncthreads();

    if (w < 2) {
        float s0 = scsm[w * 64 + lane];
        float s1 = scsm[w * 64 + 32 + lane];
        float m = fmaxf(s0, s1);
#pragma unroll
        for (int o = 16; o >= 1; o >>= 1) m = fmaxf(m, __shfl_xor_sync(0xffffffffu, m, o));
        float th = m - CAND_TH;
        int bidx = m0 + w * 64;
        if (s0 >= th) { int pos = atomicAdd(&g_count, 1); g_list[pos] = bidx + lane; }
        if (s1 >= th) { int pos = atomicAdd(&g_count, 1); g_list[pos] = bidx + 32 + lane; }
    }
}

// ---------------- kernel R: exact fp32 refinement, 16 candidates/block ----------------
// f = tid&63, g = tid>>6 handles candidates g, g+4, g+8, g+12.
__global__ void __launch_bounds__(256) kernR(const float* __restrict__ pim,
                                             const float* __restrict__ bphi) {
    __shared__ __align__(16) float psm[16][DIN];     // 48KB
    __shared__ __align__(16) float Wsm[2][64 * 64];  // 32KB
    __shared__ float redp[16][2], redd[16][2];
    __shared__ int lsm[16];
    int tid = threadIdx.x;
    int cnt = g_count;

    auto stageW = [&](int c, int s) {
        const char* src = (const char*)(g_WphiT + c * 4096) + tid * 64;
        char* dst = (char*)&Wsm[s][0] + tid * 64;
#pragma unroll
        for (int i = 0; i < 4; i++) cpa16(dst + 16 * i, src + 16 * i);
        CP_COMMIT();
    };

    for (int base = blockIdx.x * 16; base < cnt; base += gridDim.x * 16) {
        int nc = min(16, cnt - base);
        __syncthreads();
        if (tid < 16) lsm[tid] = (tid < nc) ? g_list[base + tid] : -1;
        __syncthreads();
        stageW(0, 0); stageW(1, 1);
        // stage p rows: 16 threads per row
        int row = tid >> 4, lj = tid & 15;
        if (lsm[row] >= 0) {
            const float4* src = (const float4*)(pim + (size_t)lsm[row] * DIN);
            float4* dst = (float4*)&psm[row][0];
#pragma unroll
            for (int jj = 0; jj < 12; jj++) dst[lj + 16 * jj] = src[lj + 16 * jj];
        }

        int f = tid & 63, g = tid >> 6;
        float u[4] = {0.f, 0.f, 0.f, 0.f};
        for (int c = 0; c < NCH; c++) {
            const int s = c & 1;
            CP_WAIT1();
            __syncthreads();
            const float* Ws = &Wsm[s][0];
            const float* p0 = &psm[g][c * 64];
            const float* p1 = &psm[g + 4][c * 64];
            const float* p2 = &psm[g + 8][c * 64];
            const float* p3 = &psm[g + 12][c * 64];
#pragma unroll 8
            for (int kk = 0; kk < 64; kk++) {
                float wv = Ws[kk * 64 + f];
                u[0] += wv * p0[kk];
                u[1] += wv * p1[kk];
                u[2] += wv * p2[kk];
                u[3] += wv * p3[kk];
            }
            __syncthreads();
            if (c + 2 < NCH) stageW(c + 2, s);
            else CP_COMMIT();
        }
        float bp = bphi[f];
#pragma unroll
        for (int j = 0; j < 4; j++) u[j] += bp;

        int w = tid >> 5;
#pragma unroll
        for (int j = 0; j < 4; j++) {
            int cand = lsm[g + 4 * j];
            float xf = (cand >= 0) ? g_xfeat[(cand >> 6) * 64 + f] : 0.f;
            float ps = u[j] * u[j], pd = u[j] * xf;
#pragma unroll
            for (int o = 16; o >= 1; o >>= 1) {
                ps += __shfl_xor_sync(0xffffffffu, ps, o);
                pd += __shfl_xor_sync(0xffffffffu, pd, o);
            }
            if ((tid & 31) == 0) {
                redp[g + 4 * j][w & 1] = ps;
                redd[g + 4 * j][w & 1] = pd;
            }
        }
        __syncthreads();
        if (tid < 16 && lsm[tid] >= 0) {
            float ps = redp[tid][0] + redp[tid][1];
            float pd = redd[tid][0] + redd[tid][1];
            g_exact[lsm[tid]] = pd / fmaxf(sqrtf(ps), 1e-12f);
        }
    }
}

// ---------------- kernel D: softmax + active-list weighted sum + mix + blend ----------------
__global__ void __launch_bounds__(192) kernD(const float* __restrict__ x,
                                             const float* __restrict__ p,
                                             const float* __restrict__ Wg,
                                             const float* __restrict__ bgv,
                                             const float* __restrict__ Wo,
                                             const float* __restrict__ bov,
                                             const float* __restrict__ sig_scale,
                                             const float* __restrict__ sig_shift,
                                             float* __restrict__ out) {
    __shared__ __align__(16) float buf[DIN];
    __shared__ __align__(16) float wsm[64];
    __shared__ int actsm[64];
    __shared__ float swsm;
    __shared__ int nactsm;
    int tid = threadIdx.x;
    int b = blockIdx.x;

    if (tid < 32) {
        int lane = tid;
        float s0 = g_exact[b * 64 + lane];
        float s1 = g_exact[b * 64 + 32 + lane];
        float t0 = s0 * SHARPNESS, t1 = s1 * SHARPNESS;
        float mraw = fmaxf(s0, s1), mt = fmaxf(t0, t1);
#pragma unroll
        for (int o = 16; o >= 1; o >>= 1) {
            mraw = fmaxf(mraw, __shfl_xor_sync(0xffffffffu, mraw, o));
            mt   = fmaxf(mt,   __shfl_xor_sync(0xffffffffu, mt, o));
        }
        float e0 = expf(t0 - mt), e1 = expf(t1 - mt);
        float sum = e0 + e1;
#pragma unroll
        for (int o = 16; o >= 1; o >>= 1) sum += __shfl_xor_sync(0xffffffffu, sum, o);
        float inv = 1.f / sum;
        float w0 = e0 * inv, w1 = e1 * inv;
        wsm[lane]      = w0;
        wsm[lane + 32] = w1;
        uint32_t bal0 = __ballot_sync(0xffffffffu, w0 > 1e-10f);
        uint32_t bal1 = __ballot_sync(0xffffffffu, w1 > 1e-10f);
        int c0 = __popc(bal0);
        if (w0 > 1e-10f) actsm[__popc(bal0 & ((1u << lane) - 1u))] = lane;
        if (w1 > 1e-10f) actsm[c0 + __popc(bal1 & ((1u << lane) - 1u))] = lane + 32;
        if (lane == 0) {
            nactsm = c0 + __popc(bal1);
            float z = mraw * sig_scale[0] + sig_shift[0];
            swsm = 1.f / (1.f + expf(-z));
        }
    }
    __syncthreads();

    int nact = nactsm;
    float4 acc = make_float4(0.f, 0.f, 0.f, 0.f);
    const float4* pb = (const float4*)(p + (size_t)b * KK * DIN);
    for (int j = 0; j < nact; j++) {
        int k = actsm[j];
        float w = wsm[k];
        float4 v = pb[k * 192 + tid];
        acc.x += w * v.x; acc.y += w * v.y; acc.z += w * v.z; acc.w += w * v.w;
    }
    ((float4*)buf)[tid] = acc;
    __syncthreads();

    int o = tid / 64;
    int hw = (tid % 64) * 4;
    float gg0 = Wg[o * 3 + 0], gg1 = Wg[o * 3 + 1], gg2 = Wg[o * 3 + 2];
    float bgc = bgv[o];
    float t[4];
#pragma unroll
    for (int j = 0; j < 4; j++)
        t[j] = gg0 * buf[hw + j] + gg1 * buf[256 + hw + j] + gg2 * buf[512 + hw + j] + bgc;
    __syncthreads();
#pragma unroll
    for (int j = 0; j < 4; j++) buf[o * 256 + hw + j] = t[j];
    __syncthreads();

    float oo0 = Wo[o * 3 + 0], oo1 = Wo[o * 3 + 1], oo2 = Wo[o * 3 + 2];
    float boc = bov[o];
    float sw = swsm;
    float4 xv = ((const float4*)(x + (size_t)b * DIN))[tid];
    float pa0 = oo0 * buf[hw + 0] + oo1 * buf[256 + hw + 0] + oo2 * buf[512 + hw + 0] + boc;
    float pa1 = oo0 * buf[hw + 1] + oo1 * buf[256 + hw + 1] + oo2 * buf[512 + hw + 1] + boc;
    float pa2 = oo0 * buf[hw + 2] + oo1 * buf[256 + hw + 2] + oo2 * buf[512 + hw + 2] + boc;
    float pa3 = oo0 * buf[hw + 3] + oo1 * buf[256 + hw + 3] + oo2 * buf[512 + hw + 3] + boc;
    float4 ov;
    ov.x = xv.x * (1.f - sw) + pa0 * sw;
    ov.y = xv.y * (1.f - sw) + pa1 * sw;
    ov.z = xv.z * (1.f - sw) + pa2 * sw;
    ov.w = xv.w * (1.f - sw) + pa3 * sw;
    ((float4*)(out + (size_t)b * DIN))[tid] = ov;
}

// ---------------- launch ----------------
extern "C" void kernel_launch(void* const* d_in, const int* in_sizes, int n_in,
                              void* d_out, int out_size) {
    const float* x         = (const float*)d_in[0];
    const float* p         = (const float*)d_in[1];
    const float* x_im      = (const float*)d_in[2];
    const float* p_im      = (const float*)d_in[3];
    const float* Wtheta    = (const float*)d_in[4];
    const float* btheta    = (const float*)d_in[5];
    const float* Wphi      = (const float*)d_in[6];
    const float* bphi      = (const float*)d_in[7];
    const float* Wg        = (const float*)d_in[8];
    const float* bg        = (const float*)d_in[9];
    const float* Wo        = (const float*)d_in[10];
    const float* bo        = (const float*)d_in[11];
    const float* sig_scale = (const float*)d_in[12];
    const float* sig_shift = (const float*)d_in[13];
    float* out = (float*)d_out;

    cudaFuncSetAttribute(kernB, cudaFuncAttributeMaxDynamicSharedMemorySize, SMEMB_TOTAL);

    kernEF<<<432, 256>>>(Wphi, Wtheta);
    kernA<<<BB / 16, 256>>>(x_im, btheta);
    kernB<<<MROWS / 128, 256, SMEMB_TOTAL>>>(p_im, bphi);
    kernR<<<512, 256>>>(p_im, bphi);
    kernD<<<BB, 192>>>(x, p, Wg, bg, Wo, bo, sig_scale, sig_shift, out);
}

// round 16
// speedup vs baseline: 1.6931x; 1.0143x over previous
#include <cuda_runtime.h>
#include <cuda_bf16.h>
#include <math.h>
#include <stdint.h>

// Problem constants
#define BB 2048
#define KK 64
#define DIN 768
#define CF 64
#define MROWS (BB*KK)
#define SHARPNESS 1048576.0f
#define NCH 12            // K chunks of 64
#define CAND_TH 0.03f     // approx-score gap threshold for refinement
#define RCAP 32768        // refinement slab capacity (observed cnt ~4K)

// ---------------- scratch ----------------
__device__ float g_xfeat[BB*CF];
__device__ float g_exact[MROWS];         // exact scores for candidates, -1e30 else
__device__ int   g_list[MROWS];          // candidate list (b*64+k)
__device__ int   g_count;
__device__ float g_WphiT[DIN*CF];        // Wphi transposed [k][f], fp32
__device__ float g_WthetaT[DIN*CF];      // Wtheta transposed [k][f], fp32
__device__ float g_upart[4][RCAP*64];    // partial u per K-part (32MB)
// Fragment-ordered bf16 HI images of Wphi: [c][ks][nt][lane] uint2 {h01,h23}
__device__ __align__(16) uint2 g_Bfrag[NCH*4*8*32];   // 98KB, L2-resident

// ---------------- helpers ----------------
__device__ __forceinline__ void cpa16(void* smem, const void* g) {
    unsigned s = (unsigned)__cvta_generic_to_shared(smem);
    asm volatile("cp.async.cg.shared.global [%0], [%1], 16;" :: "r"(s), "l"(g));
}
#define CP_COMMIT() asm volatile("cp.async.commit_group;")
#define CP_WAIT1()  asm volatile("cp.async.wait_group 1;" ::: "memory")

__device__ __forceinline__ uint32_t cvt_hi(float a0, float a1) {
    uint32_t hp;
    asm("cvt.rn.satfinite.bf16x2.f32 %0, %1, %2;" : "=r"(hp) : "f"(a1), "f"(a0));
    return hp;
}

__device__ __forceinline__ void mma_bf16(float* d, const uint32_t* a, uint32_t b0, uint32_t b1) {
    asm volatile("mma.sync.aligned.m16n8k16.row.col.f32.bf16.bf16.f32 "
        "{%0,%1,%2,%3}, {%4,%5,%6,%7}, {%8,%9}, {%0,%1,%2,%3};"
        : "+f"(d[0]), "+f"(d[1]), "+f"(d[2]), "+f"(d[3])
        : "r"(a[0]), "r"(a[1]), "r"(a[2]), "r"(a[3]), "r"(b0), "r"(b1));
}

// ---------------- kernel EF: fused weight preprocessing ----------------
__global__ void kernEF(const float* __restrict__ Wphi, const float* __restrict__ Wtheta) {
    int bid = blockIdx.x, tid = threadIdx.x;
    if (bid < 48) {
        int idx = bid * 256 + tid;
        int lane = idx & 31;
        int t = idx >> 5;
        int nt = t & 7, ks = (t >> 3) & 3, c = t >> 5;
        int g = lane >> 2, tig = lane & 3;
        int n = nt * 8 + g;
        int k0 = c * 64 + ks * 16 + 2 * tig;
        const float* wr = Wphi + n * DIN + k0;
        uint32_t h01 = cvt_hi(wr[0], wr[1]);
        uint32_t h23 = cvt_hi(wr[8], wr[9]);
        g_Bfrag[((c * 4 + ks) * 8 + nt) * 32 + lane] = make_uint2(h01, h23);
    } else if (bid < 240) {
        int o = (bid - 48) * 256 + tid;          // o = k*64+f
        if (o == 0) g_count = 0;
        int k = o >> 6, f = o & 63;
        g_WphiT[o] = Wphi[f * DIN + k];
    } else {
        int o = (bid - 240) * 256 + tid;
        int k = o >> 6, f = o & 63;
        g_WthetaT[o] = Wtheta[f * DIN + k];
    }
}

// ---------------- kernel A: x_feat, WthetaT chunk-staged via cp.async, 16 b/block ----------------
__global__ void __launch_bounds__(256) kernA(const float* __restrict__ xim,
                                             const float* __restrict__ btheta) {
    __shared__ __align__(16) float xs[16 * DIN];     // 48KB
    __shared__ __align__(16) float Wsm[2][64 * 64];  // 32KB
    __shared__ float wred[16][2];
    int tid = threadIdx.x;
    int b0 = blockIdx.x * 16;

    auto stageW = [&](int c, int s) {
        const char* src = (const char*)(g_WthetaT + c * 4096) + tid * 64;
        char* dst = (char*)&Wsm[s][0] + tid * 64;
#pragma unroll
        for (int i = 0; i < 4; i++) cpa16(dst + 16 * i, src + 16 * i);
        CP_COMMIT();
    };

    stageW(0, 0); stageW(1, 1);
    {
        const float4* src = (const float4*)(xim + (size_t)b0 * DIN);
        float4* d4 = (float4*)xs;
#pragma unroll
        for (int j = 0; j < 12; j++) d4[tid + 256 * j] = src[tid + 256 * j];
    }

    int f = tid & 63, q = tid >> 6;
    float acc[4] = {0.f, 0.f, 0.f, 0.f};
    for (int c = 0; c < NCH; c++) {
        const int s = c & 1;
        CP_WAIT1();
        __syncthreads();
        const float* Ws = &Wsm[s][0];
#pragma unroll 8
        for (int kk = 0; kk < 64; kk += 2) {
            float w0 = Ws[kk * 64 + f];
            float w1 = Ws[(kk + 1) * 64 + f];
#pragma unroll
            for (int j = 0; j < 4; j++) {
                float2 xv = *(const float2*)&xs[(4 * q + j) * DIN + c * 64 + kk];
                acc[j] += w0 * xv.x;
                acc[j] += w1 * xv.y;
            }
        }
        __syncthreads();
        if (c + 2 < NCH) stageW(c + 2, s);
        else CP_COMMIT();
    }
    float bt = btheta[f];
#pragma unroll
    for (int j = 0; j < 4; j++) acc[j] += bt;

    int w = tid >> 5;
    float ss[4];
#pragma unroll
    for (int j = 0; j < 4; j++) {
        ss[j] = acc[j] * acc[j];
#pragma unroll
        for (int o = 1; o < 32; o <<= 1) ss[j] += __shfl_xor_sync(0xffffffffu, ss[j], o);
    }
    if ((tid & 31) == 0) {
#pragma unroll
        for (int j = 0; j < 4; j++) wred[q * 4 + j][w & 1] = ss[j];
    }
    __syncthreads();
#pragma unroll
    for (int j = 0; j < 4; j++) {
        float n = wred[q * 4 + j][0] + wred[q * 4 + j][1];
        g_xfeat[(b0 + 4 * q + j) * CF + f] = acc[j] / fmaxf(sqrtf(n), 1e-12f);
    }
}

// ---------------- kernel B: 1-term bf16 HMMA + score epilogue + candidate selection ----------------
#define ASTR 68
#define S_A  0
#define S_B  69632
#define S_XF 86016
#define S_BP 86528
#define S_SC 86784
#define SMEMB_TOTAL 87296

__global__ void __launch_bounds__(256, 2) kernB(const float* __restrict__ pim,
                                                const float* __restrict__ bphi) {
    extern __shared__ __align__(16) char smem[];
    float* Asm = (float*)(smem + S_A);
    uint2* Bsm = (uint2*)(smem + S_B);
    float* xfsm = (float*)(smem + S_XF);
    float* bpsm = (float*)(smem + S_BP);
    float* scsm = (float*)(smem + S_SC);

    int tid = threadIdx.x, w = tid >> 5, lane = tid & 31;
    int g = lane >> 2, tig = lane & 3;
    int m0 = blockIdx.x * 128;
    if (tid < 128) xfsm[tid] = g_xfeat[m0 + tid];
    else if (tid < 192) bpsm[tid - 128] = bphi[tid - 128];

    float acc[8][4];
#pragma unroll
    for (int nt = 0; nt < 8; nt++)
#pragma unroll
        for (int i = 0; i < 4; i++) acc[nt][i] = 0.f;

    const int arow = (tid >> 4);
    const int acol = 4 * (tid & 15);
    const float* asrc = pim + (size_t)(m0 + arow) * DIN + acol;

    auto issue = [&](int c, int s) {
        float* Ad = Asm + s * (128 * ASTR);
#pragma unroll
        for (int i = 0; i < 8; i++)
            cpa16(Ad + (arow + 16 * i) * ASTR + acol, asrc + (size_t)16 * i * DIN + c * 64);
        const char* bs = (const char*)(g_Bfrag + (size_t)c * 1024) + tid * 32;
        char* bd = (char*)(Bsm + s * 1024) + tid * 32;
        cpa16(bd, bs); cpa16(bd + 16, bs + 16);
        CP_COMMIT();
    };

    issue(0, 0); issue(1, 1);

    for (int c = 0; c < NCH; c++) {
        const int s = c & 1;
        CP_WAIT1();
        __syncthreads();
        const float* As = Asm + s * (128 * ASTR);
        const uint2* Bs = Bsm + s * 1024;
        const int r0 = 16 * w + g;
#pragma unroll
        for (int ks = 0; ks < 4; ks++) {
            const int kb = 16 * ks + 2 * tig;
            float2 f0 = *(const float2*)(As + r0 * ASTR + kb);
            float2 f1 = *(const float2*)(As + (r0 + 8) * ASTR + kb);
            float2 f2 = *(const float2*)(As + r0 * ASTR + kb + 8);
            float2 f3 = *(const float2*)(As + (r0 + 8) * ASTR + kb + 8);
            uint32_t Ah[4];
            Ah[0] = cvt_hi(f0.x, f0.y);
            Ah[1] = cvt_hi(f1.x, f1.y);
            Ah[2] = cvt_hi(f2.x, f2.y);
            Ah[3] = cvt_hi(f3.x, f3.y);
#pragma unroll
            for (int nt = 0; nt < 8; nt++) {
                uint2 b = Bs[(ks * 8 + nt) * 32 + lane];
                mma_bf16(acc[nt], Ah, b.x, b.y);
            }
        }
        __syncthreads();
        if (c + 2 < NCH) issue(c + 2, s);
        else CP_COMMIT();
    }

    int bi = w >> 2;
    float ps0 = 0.f, pd0 = 0.f, ps1 = 0.f, pd1 = 0.f;
#pragma unroll
    for (int nt = 0; nt < 8; nt++) {
        int col = nt * 8 + 2 * tig;
        float b0 = bpsm[col], b1 = bpsm[col + 1];
        float x0 = xfsm[bi * 64 + col], x1 = xfsm[bi * 64 + col + 1];
        float u;
        u = acc[nt][0] + b0; ps0 += u * u; pd0 += u * x0;
        u = acc[nt][1] + b1; ps0 += u * u; pd0 += u * x1;
        u = acc[nt][2] + b0; ps1 += u * u; pd1 += u * x0;
        u = acc[nt][3] + b1; ps1 += u * u; pd1 += u * x1;
    }
#pragma unroll
    for (int o = 1; o < 4; o <<= 1) {
        ps0 += __shfl_xor_sync(0xffffffffu, ps0, o);
        pd0 += __shfl_xor_sync(0xffffffffu, pd0, o);
        ps1 += __shfl_xor_sync(0xffffffffu, ps1, o);
        pd1 += __shfl_xor_sync(0xffffffffu, pd1, o);
    }
    int lr = 16 * w + g;
    if (tig == 0) {
        scsm[lr]     = pd0 / fmaxf(sqrtf(ps0), 1e-12f);
        scsm[lr + 8] = pd1 / fmaxf(sqrtf(ps1), 1e-12f);
    }
    if (tid < 128) g_exact[m0 + tid] = -1e30f;
    __syncthreads();

    if (w < 2) {
        float s0 = scsm[w * 64 + lane];
        float s1 = scsm[w * 64 + 32 + lane];
        float m = fmaxf(s0, s1);
#pragma unroll
        for (int o = 16; o >= 1; o >>= 1) m = fmaxf(m, __shfl_xor_sync(0xffffffffu, m, o));
        float th = m - CAND_TH;
        int bidx = m0 + w * 64;
        if (s0 >= th) { int pos = atomicAdd(&g_count, 1); if (pos < RCAP) g_list[pos] = bidx + lane; }
        if (s1 >= th) { int pos = atomicAdd(&g_count, 1); if (pos < RCAP) g_list[pos] = bidx + 32 + lane; }
    }
}

// ---------------- kernel RP: partial exact u over one K-part (3 chunks) ----------------
// grid = 1024: part = blockIdx&3, candGroup = blockIdx>>2 (256 groups x 16 cands)
// 256 threads: f = tid&63, g = tid>>6 handles local cands g, g+4, g+8, g+12.
__global__ void __launch_bounds__(256) kernRP(const float* __restrict__ pim) {
    __shared__ __align__(16) float psm[16][192];     // 12KB (this part's K slice)
    __shared__ __align__(16) float Wsm[2][64 * 64];  // 32KB
    __shared__ int lsm[16];
    int tid = threadIdx.x;
    int part = blockIdx.x & 3;
    int grp = blockIdx.x >> 2;
    int cnt = min(g_count, RCAP);
    const int c0 = part * 3;                          // first global chunk of this part

    auto stageW = [&](int j, int s) {
        const char* src = (const char*)(g_WphiT + (c0 + j) * 4096) + tid * 64;
        char* dst = (char*)&Wsm[s][0] + tid * 64;
#pragma unroll
        for (int i = 0; i < 4; i++) cpa16(dst + 16 * i, src + 16 * i);
        CP_COMMIT();
    };

    for (int base = grp * 16; base < cnt; base += 256 * 16) {
        __syncthreads();
        if (tid < 16) lsm[tid] = (base + tid < cnt) ? g_list[base + tid] : -1;
        __syncthreads();
        stageW(0, 0); stageW(1, 1);
        // stage p K-slices: 16 threads per row, 3 float4 each
        int row = tid >> 4, lj = tid & 15;
        if (lsm[row] >= 0) {
            const float4* src = (const float4*)(pim + (size_t)lsm[row] * DIN + part * 192);
            float4* dst = (float4*)&psm[row][0];
#pragma unroll
            for (int jj = 0; jj < 3; jj++) dst[lj + 16 * jj] = src[lj + 16 * jj];
        }

        int f = tid & 63, g = tid >> 6;
        float u[4] = {0.f, 0.f, 0.f, 0.f};
#pragma unroll
        for (int j = 0; j < 3; j++) {
            const int s = j & 1;
            CP_WAIT1();
            __syncthreads();
            const float* Ws = &Wsm[s][0];
#pragma unroll 4
            for (int kk = 0; kk < 64; kk += 4) {
                float w0 = Ws[kk * 64 + f];
                float w1 = Ws[(kk + 1) * 64 + f];
                float w2 = Ws[(kk + 2) * 64 + f];
                float w3 = Ws[(kk + 3) * 64 + f];
#pragma unroll
                for (int q = 0; q < 4; q++) {
                    float4 pv = *(const float4*)&psm[g + 4 * q][j * 64 + kk];
                    u[q] += w0 * pv.x + w1 * pv.y + w2 * pv.z + w3 * pv.w;
                }
            }
            __syncthreads();
            if (j + 2 < 3) stageW(j + 2, s);
            else CP_COMMIT();
        }
#pragma unroll
        for (int q = 0; q < 4; q++) {
            int slot = base + g + 4 * q;
            if (lsm[g + 4 * q] >= 0)
                g_upart[part][(size_t)slot * 64 + f] = u[q];
        }
    }
}

// ---------------- kernel F: finalize exact scores (warp per candidate) ----------------
__global__ void __launch_bounds__(256) kernF(const float* __restrict__ bphi) {
    int tid = threadIdx.x, wid = tid >> 5, lane = tid & 31;
    int cnt = min(g_count, RCAP);
    for (int i = blockIdx.x * 8 + wid; i < cnt; i += gridDim.x * 8) {
        int cand = g_list[i];
        float u0 = bphi[lane], u1 = bphi[lane + 32];
#pragma unroll
        for (int part = 0; part < 4; part++) {
            u0 += g_upart[part][(size_t)i * 64 + lane];
            u1 += g_upart[part][(size_t)i * 64 + lane + 32];
        }
        int b = cand >> 6;
        float xf0 = g_xfeat[b * 64 + lane];
        float xf1 = g_xfeat[b * 64 + lane + 32];
        float ps = u0 * u0 + u1 * u1;
        float pd = u0 * xf0 + u1 * xf1;
#pragma unroll
        for (int o = 16; o >= 1; o >>= 1) {
            ps += __shfl_xor_sync(0xffffffffu, ps, o);
            pd += __shfl_xor_sync(0xffffffffu, pd, o);
        }
        if (lane == 0) g_exact[cand] = pd / fmaxf(sqrtf(ps), 1e-12f);
    }
}

// ---------------- kernel D: softmax + active-list weighted sum + mix + blend ----------------
__global__ void __launch_bounds__(192) kernD(const float* __restrict__ x,
                                             const float* __restrict__ p,
                                             const float* __restrict__ Wg,
                                             const float* __restrict__ bgv,
                                             const float* __restrict__ Wo,
                                             const float* __restrict__ bov,
                                             const float* __restrict__ sig_scale,
                                             const float* __restrict__ sig_shift,
                                             float* __restrict__ out) {
    __shared__ __align__(16) float buf[DIN];
    __shared__ __align__(16) float wsm[64];
    __shared__ int actsm[64];
    __shared__ float swsm;
    __shared__ int nactsm;
    int tid = threadIdx.x;
    int b = blockIdx.x;

    if (tid < 32) {
        int lane = tid;
        float s0 = g_exact[b * 64 + lane];
        float s1 = g_exact[b * 64 + 32 + lane];
        float t0 = s0 * SHARPNESS, t1 = s1 * SHARPNESS;
        float mraw = fmaxf(s0, s1), mt = fmaxf(t0, t1);
#pragma unroll
        for (int o = 16; o >= 1; o >>= 1) {
            mraw = fmaxf(mraw, __shfl_xor_sync(0xffffffffu, mraw, o));
            mt   = fmaxf(mt,   __shfl_xor_sync(0xffffffffu, mt, o));
        }
        float e0 = expf(t0 - mt), e1 = expf(t1 - mt);
        float sum = e0 + e1;
#pragma unroll
        for (int o = 16; o >= 1; o >>= 1) sum += __shfl_xor_sync(0xffffffffu, sum, o);
        float inv = 1.f / sum;
        float w0 = e0 * inv, w1 = e1 * inv;
        wsm[lane]      = w0;
        wsm[lane + 32] = w1;
        uint32_t bal0 = __ballot_sync(0xffffffffu, w0 > 1e-10f);
        uint32_t bal1 = __ballot_sync(0xffffffffu, w1 > 1e-10f);
        int c0 = __popc(bal0);
        if (w0 > 1e-10f) actsm[__popc(bal0 & ((1u << lane) - 1u))] = lane;
        if (w1 > 1e-10f) actsm[c0 + __popc(bal1 & ((1u << lane) - 1u))] = lane + 32;
        if (lane == 0) {
            nactsm = c0 + __popc(bal1);
            float z = mraw * sig_scale[0] + sig_shift[0];
            swsm = 1.f / (1.f + expf(-z));
        }
    }
    __syncthreads();

    int nact = nactsm;
    float4 acc = make_float4(0.f, 0.f, 0.f, 0.f);
    const float4* pb = (const float4*)(p + (size_t)b * KK * DIN);
    for (int j = 0; j < nact; j++) {
        int k = actsm[j];
        float w = wsm[k];
        float4 v = pb[k * 192 + tid];
        acc.x += w * v.x; acc.y += w * v.y; acc.z += w * v.z; acc.w += w * v.w;
    }
    ((float4*)buf)[tid] = acc;
    __syncthreads();

    int o = tid / 64;
    int hw = (tid % 64) * 4;
    float gg0 = Wg[o * 3 + 0], gg1 = Wg[o * 3 + 1], gg2 = Wg[o * 3 + 2];
    float bgc = bgv[o];
    float t[4];
#pragma unroll
    for (int j = 0; j < 4; j++)
        t[j] = gg0 * buf[hw + j] + gg1 * buf[256 + hw + j] + gg2 * buf[512 + hw + j] + bgc;
    __syncthreads();
#pragma unroll
    for (int j = 0; j < 4; j++) buf[o * 256 + hw + j] = t[j];
    __syncthreads();

    float oo0 = Wo[o * 3 + 0], oo1 = Wo[o * 3 + 1], oo2 = Wo[o * 3 + 2];
    float boc = bov[o];
    float sw = swsm;
    float4 xv = ((const float4*)(x + (size_t)b * DIN))[tid];
    float pa0 = oo0 * buf[hw + 0] + oo1 * buf[256 + hw + 0] + oo2 * buf[512 + hw + 0] + boc;
    float pa1 = oo0 * buf[hw + 1] + oo1 * buf[256 + hw + 1] + oo2 * buf[512 + hw + 1] + boc;
    float pa2 = oo0 * buf[hw + 2] + oo1 * buf[256 + hw + 2] + oo2 * buf[512 + hw + 2] + boc;
    float pa3 = oo0 * buf[hw + 3] + oo1 * buf[256 + hw + 3] + oo2 * buf[512 + hw + 3] + boc;
    float4 ov;
    ov.x = xv.x * (1.f - sw) + pa0 * sw;
    ov.y = xv.y * (1.f - sw) + pa1 * sw;
    ov.z = xv.z * (1.f - sw) + pa2 * sw;
    ov.w = xv.w * (1.f - sw) + pa3 * sw;
    ((float4*)(out + (size_t)b * DIN))[tid] = ov;
}

// ---------------- launch ----------------
extern "C" void kernel_launch(void* const* d_in, const int* in_sizes, int n_in,
                              void* d_out, int out_size) {
    const float* x         = (const float*)d_in[0];
    const float* p         = (const float*)d_in[1];
    const float* x_im      = (const float*)d_in[2];
    const float* p_im      = (const float*)d_in[3];
    const float* Wtheta    = (const float*)d_in[4];
    const float* btheta    = (const float*)d_in[5];
    const float* Wphi      = (const float*)d_in[6];
    const float* bphi      = (const float*)d_in[7];
    const float* Wg        = (const float*)d_in[8];
    const float* bg        = (const float*)d_in[9];
    const float* Wo        = (const float*)d_in[10];
    const float* bo        = (const float*)d_in[11];
    const float* sig_scale = (const float*)d_in[12];
    const float* sig_shift = (const float*)d_in[13];
    float* out = (float*)d_out;

    cudaFuncSetAttribute(kernB, cudaFuncAttributeMaxDynamicSharedMemorySize, SMEMB_TOTAL);

    kernEF<<<432, 256>>>(Wphi, Wtheta);
    kernA<<<BB / 16, 256>>>(x_im, btheta);
    kernB<<<MROWS / 128, 256, SMEMB_TOTAL>>>(p_im, bphi);
    kernRP<<<1024, 256>>>(p_im);
    kernF<<<64, 256>>>(bphi);
    kernD<<<BB, 192>>>(x, p, Wg, bg, Wo, bo, sig_scale, sig_shift, out);
}